// round 1
// baseline (speedup 1.0000x reference)
#include <cuda_runtime.h>
#include <math.h>

#define BB 2
#define TT 2048
#define NH 16
#define NKV 4
#define HD 64
#define DMODEL 1024
#define NTOK (BB*TT)

// Scratch (device globals; allocation-free per harness rules)
__device__ float g_q[(size_t)BB*NH*TT*HD];    // [B,H,T,D]
__device__ float g_k[(size_t)BB*NKV*TT*HD];   // [B,KV,T,D]
__device__ float g_v[(size_t)BB*NKV*TT*HD];   // [B,KV,T,D]
__device__ float g_ao[(size_t)NTOK*DMODEL];   // [B*T, H*D]

// ---------------------------------------------------------------------------
// Kernel A: QKV projection fused with RMSNorm + RoPE.
// grid = (NTOK/64, 24): y in [0,16) -> q head, [16,20) -> k head, [20,24) -> v head
// ---------------------------------------------------------------------------
__global__ __launch_bounds__(256) void qkv_kernel(
    const float* __restrict__ x,  const float* __restrict__ wq,
    const float* __restrict__ wk, const float* __restrict__ wv,
    const float* __restrict__ cosb, const float* __restrict__ sinb,
    const float* __restrict__ qn_w, const float* __restrict__ kn_w)
{
    __shared__ float xs[64][17];
    __shared__ float ws[16][65];
    __shared__ float res[64][65];

    const int tid = threadIdx.x;
    const int bm = blockIdx.x;
    const int hc = blockIdx.y;

    const float* W; int ldw, kind, head;
    if (hc < 16)      { W = wq; ldw = DMODEL; head = hc;      kind = 0; }
    else if (hc < 20) { W = wk; ldw = NKV*HD; head = hc - 16; kind = 1; }
    else              { W = wv; ldw = NKV*HD; head = hc - 20; kind = 2; }
    const int coloff = head * HD;

    const int tx = tid & 15, ty = tid >> 4;
    const int r0 = ty * 4, c0 = tx * 4;
    const int m0 = bm * 64;

    const int lr = tid >> 2, lk = (tid & 3) * 4;   // x-tile load mapping
    const int wkk = tid >> 4, wc = (tid & 15) * 4; // w-tile load mapping

    float acc[4][4] = {};

    for (int k0 = 0; k0 < DMODEL; k0 += 16) {
        float4 xv = *(const float4*)(x + (size_t)(m0 + lr) * DMODEL + k0 + lk);
        xs[lr][lk+0] = xv.x; xs[lr][lk+1] = xv.y; xs[lr][lk+2] = xv.z; xs[lr][lk+3] = xv.w;
        float4 w4 = *(const float4*)(W + (size_t)(k0 + wkk) * ldw + coloff + wc);
        ws[wkk][wc+0] = w4.x; ws[wkk][wc+1] = w4.y; ws[wkk][wc+2] = w4.z; ws[wkk][wc+3] = w4.w;
        __syncthreads();
        #pragma unroll
        for (int kk = 0; kk < 16; kk++) {
            float a[4], b[4];
            #pragma unroll
            for (int i = 0; i < 4; i++) a[i] = xs[r0 + i][kk];
            #pragma unroll
            for (int j = 0; j < 4; j++) b[j] = ws[kk][c0 + j];
            #pragma unroll
            for (int i = 0; i < 4; i++)
                #pragma unroll
                for (int j = 0; j < 4; j++)
                    acc[i][j] = fmaf(a[i], b[j], acc[i][j]);
        }
        __syncthreads();
    }

    #pragma unroll
    for (int i = 0; i < 4; i++)
        #pragma unroll
        for (int j = 0; j < 4; j++)
            res[r0 + i][c0 + j] = acc[i][j];
    __syncthreads();

    // RMSNorm + RoPE in-place (q/k only), one thread per row
    if (kind != 2 && tid < 64) {
        const int r = tid;
        const int t = (m0 + r) % TT;
        float ss = 0.f;
        #pragma unroll
        for (int j = 0; j < HD; j++) { float v = res[r][j]; ss = fmaf(v, v, ss); }
        const float inv = rsqrtf(ss * (1.0f / HD) + 1e-6f);
        const float* nw = (kind == 0) ? qn_w : kn_w;
        #pragma unroll
        for (int j = 0; j < 32; j++) {
            float a  = res[r][j]      * inv * nw[j];
            float bq = res[r][j + 32] * inv * nw[j + 32];
            float c = cosb[t * 32 + j];
            float s = sinb[t * 32 + j];
            res[r][j]      = a * c - bq * s;
            res[r][j + 32] = bq * c + a * s;
        }
    }
    __syncthreads();

    // coalesced float4 store to transposed layout (64 rows contiguous per head)
    const int b  = m0 / TT;
    const int t0 = m0 % TT;
    float* dst;
    if (kind == 0)      dst = g_q + ((size_t)(b * NH  + head) * TT + t0) * HD;
    else if (kind == 1) dst = g_k + ((size_t)(b * NKV + head) * TT + t0) * HD;
    else                dst = g_v + ((size_t)(b * NKV + head) * TT + t0) * HD;
    {
        int rbase = tid >> 4, c = (tid & 15) * 4;
        #pragma unroll
        for (int rr = rbase; rr < 64; rr += 16) {
            float4 o4 = make_float4(res[rr][c], res[rr][c+1], res[rr][c+2], res[rr][c+3]);
            *(float4*)(dst + (size_t)rr * HD + c) = o4;
        }
    }
}

// ---------------------------------------------------------------------------
// Kernel B: causal flash attention, fp32. grid = (T/64, B*H), 256 threads.
// Q/KP/V tiles each 64x64 fp32 => exactly 48KB static smem.
// KP holds K (xor-swizzled columns), then is reused for P.
// ---------------------------------------------------------------------------
__global__ __launch_bounds__(256) void attn_kernel()
{
    __shared__ float Qs[64][64];
    __shared__ float KP[64][64];
    __shared__ float Vs[64][64];

    const int tid = threadIdx.x;
    const int tx = tid & 15, ty = tid >> 4;
    const int r0 = ty * 4, c0 = tx * 4;

    const int qb  = gridDim.x - 1 - blockIdx.x;  // heavy blocks first
    const int bh  = blockIdx.y;
    const int b   = bh >> 4, h = bh & 15;
    const int kvh = h >> 2;                      // GQA: n_rep = 4

    const float* Qg = g_q + ((size_t)(b * NH  + h)   * TT + qb * 64) * HD;
    const float* Kg = g_k + ((size_t)(b * NKV + kvh) * TT) * HD;
    const float* Vg = g_v + ((size_t)(b * NKV + kvh) * TT) * HD;

    for (int e = tid; e < 1024; e += 256) {
        int r = e >> 4, c = (e & 15) << 2;
        float4 v4 = *(const float4*)(Qg + r * HD + c);
        Qs[r][c] = v4.x; Qs[r][c+1] = v4.y; Qs[r][c+2] = v4.z; Qs[r][c+3] = v4.w;
    }

    float o[4][4] = {};
    float m_i[4], l_i[4];
    #pragma unroll
    for (int i = 0; i < 4; i++) { m_i[i] = -1e30f; l_i[i] = 0.f; }

    for (int kb = 0; kb <= qb; kb++) {
        __syncthreads();  // previous iter's KP/Vs reads done (also covers Qs load)
        for (int e = tid; e < 1024; e += 256) {
            int r = e >> 4, c = (e & 15) << 2;
            float4 k4 = *(const float4*)(Kg + (size_t)(kb * 64 + r) * HD + c);
            int xr = r & 31;
            KP[r][(c+0) ^ xr] = k4.x;
            KP[r][(c+1) ^ xr] = k4.y;
            KP[r][(c+2) ^ xr] = k4.z;
            KP[r][(c+3) ^ xr] = k4.w;
            float4 v4 = *(const float4*)(Vg + (size_t)(kb * 64 + r) * HD + c);
            Vs[r][c] = v4.x; Vs[r][c+1] = v4.y; Vs[r][c+2] = v4.z; Vs[r][c+3] = v4.w;
        }
        __syncthreads();

        // S = Q @ K^T (per-thread 4x4)
        float s[4][4] = {};
        #pragma unroll 16
        for (int d = 0; d < 64; d++) {
            float a[4], bb[4];
            #pragma unroll
            for (int i = 0; i < 4; i++) a[i] = Qs[r0 + i][d];
            #pragma unroll
            for (int j = 0; j < 4; j++) bb[j] = KP[c0 + j][d ^ ((c0 + j) & 31)];
            #pragma unroll
            for (int i = 0; i < 4; i++)
                #pragma unroll
                for (int j = 0; j < 4; j++)
                    s[i][j] = fmaf(a[i], bb[j], s[i][j]);
        }

        // scale + causal mask + online softmax (row stats via 16-lane shuffles)
        float c_i[4];
        const bool diag = (kb == qb);
        #pragma unroll
        for (int i = 0; i < 4; i++) {
            #pragma unroll
            for (int j = 0; j < 4; j++) {
                float sv = s[i][j] * 0.125f;
                if (diag && (c0 + j) > (r0 + i)) sv = -1e30f;
                s[i][j] = sv;
            }
            float mloc = fmaxf(fmaxf(s[i][0], s[i][1]), fmaxf(s[i][2], s[i][3]));
            #pragma unroll
            for (int off = 8; off > 0; off >>= 1)
                mloc = fmaxf(mloc, __shfl_xor_sync(0xffffffffu, mloc, off));
            float mnew = fmaxf(m_i[i], mloc);
            float ci = __expf(m_i[i] - mnew);
            float ps = 0.f;
            #pragma unroll
            for (int j = 0; j < 4; j++) {
                float p = __expf(s[i][j] - mnew);
                s[i][j] = p;
                ps += p;
            }
            #pragma unroll
            for (int off = 8; off > 0; off >>= 1)
                ps += __shfl_xor_sync(0xffffffffu, ps, off);
            l_i[i] = l_i[i] * ci + ps;
            m_i[i] = mnew;
            c_i[i] = ci;
        }

        __syncthreads();  // all K reads complete before P overwrites KP
        #pragma unroll
        for (int i = 0; i < 4; i++) {
            int rr = r0 + i, xr = rr & 31;
            #pragma unroll
            for (int j = 0; j < 4; j++)
                KP[rr][(c0 + j) ^ xr] = s[i][j];
        }
        __syncthreads();

        #pragma unroll
        for (int i = 0; i < 4; i++)
            #pragma unroll
            for (int j = 0; j < 4; j++)
                o[i][j] *= c_i[i];

        // O += P @ V
        #pragma unroll 16
        for (int j = 0; j < 64; j++) {
            float p[4], vv[4];
            #pragma unroll
            for (int i = 0; i < 4; i++) p[i] = KP[r0 + i][j ^ ((r0 + i) & 31)];
            #pragma unroll
            for (int jj = 0; jj < 4; jj++) vv[jj] = Vs[j][c0 + jj];
            #pragma unroll
            for (int i = 0; i < 4; i++)
                #pragma unroll
                for (int jj = 0; jj < 4; jj++)
                    o[i][jj] = fmaf(p[i], vv[jj], o[i][jj]);
        }
    }

    #pragma unroll
    for (int i = 0; i < 4; i++) {
        float invl = 1.0f / l_i[i];
        float4 o4 = make_float4(o[i][0]*invl, o[i][1]*invl, o[i][2]*invl, o[i][3]*invl);
        size_t t = (size_t)(b * TT + qb * 64 + r0 + i);
        *(float4*)(g_ao + t * DMODEL + h * HD + c0) = o4;
    }
}

// ---------------------------------------------------------------------------
// Kernel C: output projection  out = g_ao @ wo.  grid = (NTOK/64, DM/64)
// ---------------------------------------------------------------------------
__global__ __launch_bounds__(256) void out_kernel(
    const float* __restrict__ wo, float* __restrict__ out)
{
    __shared__ float xs[64][17];
    __shared__ float ws[16][65];

    const int tid = threadIdx.x;
    const int bm = blockIdx.x, bn = blockIdx.y;
    const int tx = tid & 15, ty = tid >> 4;
    const int r0 = ty * 4, c0 = tx * 4;
    const int m0 = bm * 64, n0 = bn * 64;

    const int lr = tid >> 2, lk = (tid & 3) * 4;
    const int wkk = tid >> 4, wc = (tid & 15) * 4;

    float acc[4][4] = {};

    for (int k0 = 0; k0 < DMODEL; k0 += 16) {
        float4 xv = *(const float4*)(g_ao + (size_t)(m0 + lr) * DMODEL + k0 + lk);
        xs[lr][lk+0] = xv.x; xs[lr][lk+1] = xv.y; xs[lr][lk+2] = xv.z; xs[lr][lk+3] = xv.w;
        float4 w4 = *(const float4*)(wo + (size_t)(k0 + wkk) * DMODEL + n0 + wc);
        ws[wkk][wc+0] = w4.x; ws[wkk][wc+1] = w4.y; ws[wkk][wc+2] = w4.z; ws[wkk][wc+3] = w4.w;
        __syncthreads();
        #pragma unroll
        for (int kk = 0; kk < 16; kk++) {
            float a[4], b[4];
            #pragma unroll
            for (int i = 0; i < 4; i++) a[i] = xs[r0 + i][kk];
            #pragma unroll
            for (int j = 0; j < 4; j++) b[j] = ws[kk][c0 + j];
            #pragma unroll
            for (int i = 0; i < 4; i++)
                #pragma unroll
                for (int j = 0; j < 4; j++)
                    acc[i][j] = fmaf(a[i], b[j], acc[i][j]);
        }
        __syncthreads();
    }

    #pragma unroll
    for (int i = 0; i < 4; i++) {
        float4 o4 = make_float4(acc[i][0], acc[i][1], acc[i][2], acc[i][3]);
        *(float4*)(out + (size_t)(m0 + r0 + i) * DMODEL + n0 + c0) = o4;
    }
}

// ---------------------------------------------------------------------------
extern "C" void kernel_launch(void* const* d_in, const int* in_sizes, int n_in,
                              void* d_out, int out_size) {
    const float* x    = (const float*)d_in[0];
    const float* cosb = (const float*)d_in[1];
    const float* sinb = (const float*)d_in[2];
    const float* wq   = (const float*)d_in[3];
    const float* wk   = (const float*)d_in[4];
    const float* wv   = (const float*)d_in[5];
    const float* wo   = (const float*)d_in[6];
    const float* qn_w = (const float*)d_in[7];
    const float* kn_w = (const float*)d_in[8];
    float* out = (float*)d_out;

    dim3 gA(NTOK / 64, 24);
    qkv_kernel<<<gA, 256>>>(x, wq, wk, wv, cosb, sinb, qn_w, kn_w);

    dim3 gB(TT / 64, BB * NH);
    attn_kernel<<<gB, 256>>>();

    dim3 gC(NTOK / 64, DMODEL / 64);
    out_kernel<<<gC, 256>>>(wo, out);
}

// round 2
// speedup vs baseline: 1.4007x; 1.4007x over previous
#include <cuda_runtime.h>
#include <math.h>

#define BB 2
#define TT 2048
#define NH 16
#define NKV 4
#define HD 64
#define DMODEL 1024
#define NTOK (BB*TT)

// Scratch (device globals; allocation-free per harness rules)
__device__ float g_q[(size_t)BB*NH*TT*HD];    // [B,H,T,D]
__device__ float g_k[(size_t)BB*NKV*TT*HD];   // [B,KV,T,D]
__device__ float g_v[(size_t)BB*NKV*TT*HD];   // [B,KV,T,D]
__device__ float g_ao[(size_t)NTOK*DMODEL];   // [B*T, H*D]

// ---------------------------------------------------------------------------
// Kernel A: QKV projection (128x128 tile, 8x8 micro, double-buffered) fused
// with register-resident RMSNorm + RoPE epilogue.
// grid = (NTOK/128, 12): y 0-7 -> Q cols, 8-9 -> K cols, 10-11 -> V cols
// ---------------------------------------------------------------------------
__global__ __launch_bounds__(256) void qkv_kernel(
    const float* __restrict__ x,  const float* __restrict__ wq,
    const float* __restrict__ wk, const float* __restrict__ wv,
    const float* __restrict__ cosb, const float* __restrict__ sinb,
    const float* __restrict__ qn_w, const float* __restrict__ kn_w)
{
    __shared__ float As[2][8][132];   // K-major A
    __shared__ float Bs[2][8][132];

    const int tid = threadIdx.x;
    const int tx = tid & 15, ty = tid >> 4;
    const int m0 = blockIdx.x * 128;
    const int nblk = blockIdx.y;

    const float* W; int ldw, kind, n0w;
    if (nblk < 8)       { W = wq; ldw = 1024; n0w = nblk * 128;        kind = 0; }
    else if (nblk < 10) { W = wk; ldw = 256;  n0w = (nblk - 8) * 128;  kind = 1; }
    else                { W = wv; ldw = 256;  n0w = (nblk - 10) * 128; kind = 2; }

    const int am = tid >> 1, ak = (tid & 1) * 4;
    const int bk = tid >> 5, bn = (tid & 31) * 4;

    float acc[8][8] = {};

    float4 a4 = *(const float4*)(x + (size_t)(m0 + am) * DMODEL + ak);
    float4 b4 = *(const float4*)(W + (size_t)bk * ldw + n0w + bn);
    As[0][ak+0][am] = a4.x; As[0][ak+1][am] = a4.y;
    As[0][ak+2][am] = a4.z; As[0][ak+3][am] = a4.w;
    *(float4*)&Bs[0][bk][bn] = b4;
    __syncthreads();

    int buf = 0;
    for (int k0 = 0; k0 < DMODEL; k0 += 8) {
        const bool more = (k0 + 8 < DMODEL);
        if (more) {
            a4 = *(const float4*)(x + (size_t)(m0 + am) * DMODEL + k0 + 8 + ak);
            b4 = *(const float4*)(W + (size_t)(k0 + 8 + bk) * ldw + n0w + bn);
        }
        #pragma unroll
        for (int kk = 0; kk < 8; kk++) {
            float a[8], b[8];
            *(float4*)(a)     = *(const float4*)&As[buf][kk][ty*8];
            *(float4*)(a + 4) = *(const float4*)&As[buf][kk][ty*8 + 4];
            *(float4*)(b)     = *(const float4*)&Bs[buf][kk][tx*8];
            *(float4*)(b + 4) = *(const float4*)&Bs[buf][kk][tx*8 + 4];
            #pragma unroll
            for (int i = 0; i < 8; i++)
                #pragma unroll
                for (int j = 0; j < 8; j++)
                    acc[i][j] = fmaf(a[i], b[j], acc[i][j]);
        }
        if (more) {
            As[buf^1][ak+0][am] = a4.x; As[buf^1][ak+1][am] = a4.y;
            As[buf^1][ak+2][am] = a4.z; As[buf^1][ak+3][am] = a4.w;
            *(float4*)&Bs[buf^1][bk][bn] = b4;
            __syncthreads();
            buf ^= 1;
        }
    }

    // ---- epilogue: RMSNorm + RoPE (Q/K), then store to [B,H,T,D] ----
    const int hloc = tx >> 3;               // which of the 2 heads in this tile
    const int dbase = (tx & 7) * 8;         // d offset within head (0..56)
    const float* nw = (kind == 0) ? qn_w : kn_w;

    #pragma unroll
    for (int i = 0; i < 8; i++) {
        const int row = m0 + ty * 8 + i;
        const int b   = row >> 11;
        const int tpos = row & 2047;

        if (kind != 2) {
            float ss = 0.f;
            #pragma unroll
            for (int j = 0; j < 8; j++) ss = fmaf(acc[i][j], acc[i][j], ss);
            ss += __shfl_xor_sync(0xffffffffu, ss, 1);
            ss += __shfl_xor_sync(0xffffffffu, ss, 2);
            ss += __shfl_xor_sync(0xffffffffu, ss, 4);
            const float inv = rsqrtf(ss * (1.0f / HD) + 1e-6f);
            #pragma unroll
            for (int j = 0; j < 8; j++) {
                const int hc = dbase + j;
                float v = acc[i][j] * inv * nw[hc];
                float p = __shfl_xor_sync(0xffffffffu, v, 4);
                const int ri = hc & 31;
                float c = cosb[tpos * 32 + ri];
                float s = sinb[tpos * 32 + ri];
                acc[i][j] = (hc < 32) ? (v * c - p * s) : (v * c + p * s);
            }
        }

        float* dst;
        if (kind == 0) {
            int h = nblk * 2 + hloc;
            dst = g_q + (((size_t)(b * NH + h)) * TT + tpos) * HD + dbase;
        } else if (kind == 1) {
            int h = (nblk - 8) * 2 + hloc;
            dst = g_k + (((size_t)(b * NKV + h)) * TT + tpos) * HD + dbase;
        } else {
            int h = (nblk - 10) * 2 + hloc;
            dst = g_v + (((size_t)(b * NKV + h)) * TT + tpos) * HD + dbase;
        }
        *(float4*)(dst)     = make_float4(acc[i][0], acc[i][1], acc[i][2], acc[i][3]);
        *(float4*)(dst + 4) = make_float4(acc[i][4], acc[i][5], acc[i][6], acc[i][7]);
    }
}

// ---------------------------------------------------------------------------
// Kernel B: causal flash attention, 128q x 128k tiles, 8x8 micro for S,
// 8x4 for O. Q/K stored d-major in smem; P staged in smem.
// grid = (T/128, B*H), 256 threads, ~172KB dynamic smem (1 CTA/SM).
// ---------------------------------------------------------------------------
#define QT_LD 132
#define VS_LD 68
#define PS_LD 136
#define SM_QT 0
#define SM_KT (SM_QT + 64*QT_LD)
#define SM_VS (SM_KT + 64*QT_LD)
#define SM_PS (SM_VS + 128*VS_LD)
#define SM_TOTAL ((SM_PS + 128*PS_LD) * 4)

__global__ __launch_bounds__(256, 1) void attn_kernel()
{
    extern __shared__ float sm[];
    float* Qt = sm + SM_QT;   // [64][132] d-major
    float* Kt = sm + SM_KT;   // [64][132] d-major
    float* Vs = sm + SM_VS;   // [128][68]
    float* Ps = sm + SM_PS;   // [128][136]

    const int tid = threadIdx.x;
    const int tx = tid & 15, ty = tid >> 4;

    const int qb = gridDim.x - 1 - blockIdx.x;   // heavy blocks first
    const int bh = blockIdx.y;
    const int b  = bh >> 4, h = bh & 15;
    const int kvh = h >> 2;

    const float* Qg = g_q + ((size_t)(b * NH  + h)   * TT + qb * 128) * HD;
    const float* Kg = g_k + ((size_t)(b * NKV + kvh) * TT) * HD;
    const float* Vg = g_v + ((size_t)(b * NKV + kvh) * TT) * HD;

    // load Q tile (transpose to d-major)
    {
        const int r = tid >> 1, dq = (tid & 1) * 32;
        #pragma unroll
        for (int t = 0; t < 8; t++) {
            const int d0 = dq + t * 4;
            float4 v = *(const float4*)(Qg + (size_t)r * HD + d0);
            Qt[(d0+0)*QT_LD + r] = v.x; Qt[(d0+1)*QT_LD + r] = v.y;
            Qt[(d0+2)*QT_LD + r] = v.z; Qt[(d0+3)*QT_LD + r] = v.w;
        }
    }

    float o[8][4] = {};
    float m_i[8], l_i[8];
    #pragma unroll
    for (int i = 0; i < 8; i++) { m_i[i] = -1e30f; l_i[i] = 0.f; }

    for (int kb = 0; kb <= qb; kb++) {
        __syncthreads();  // prior iter done reading Kt/Vs/Ps (also fences Qt load)
        {
            const int r = tid >> 1, dq = (tid & 1) * 32;
            #pragma unroll
            for (int t = 0; t < 8; t++) {
                const int d0 = dq + t * 4;
                float4 kv = *(const float4*)(Kg + (size_t)(kb*128 + r) * HD + d0);
                Kt[(d0+0)*QT_LD + r] = kv.x; Kt[(d0+1)*QT_LD + r] = kv.y;
                Kt[(d0+2)*QT_LD + r] = kv.z; Kt[(d0+3)*QT_LD + r] = kv.w;
                float4 vv = *(const float4*)(Vg + (size_t)(kb*128 + r) * HD + d0);
                *(float4*)&Vs[r*VS_LD + d0] = vv;
            }
        }
        __syncthreads();

        // S = Q K^T
        float s[8][8] = {};
        #pragma unroll 8
        for (int d = 0; d < 64; d++) {
            float a[8], bb[8];
            *(float4*)(a)      = *(const float4*)&Qt[d*QT_LD + ty*8];
            *(float4*)(a + 4)  = *(const float4*)&Qt[d*QT_LD + ty*8 + 4];
            *(float4*)(bb)     = *(const float4*)&Kt[d*QT_LD + tx*8];
            *(float4*)(bb + 4) = *(const float4*)&Kt[d*QT_LD + tx*8 + 4];
            #pragma unroll
            for (int i = 0; i < 8; i++)
                #pragma unroll
                for (int j = 0; j < 8; j++)
                    s[i][j] = fmaf(a[i], bb[j], s[i][j]);
        }

        // scale + causal + online softmax
        float c_i[8];
        const bool diag = (kb == qb);
        #pragma unroll
        for (int i = 0; i < 8; i++) {
            const int grow = ty * 8 + i;
            #pragma unroll
            for (int j = 0; j < 8; j++) {
                float sv = s[i][j] * 0.125f;
                if (diag && (tx * 8 + j) > grow) sv = -1e30f;
                s[i][j] = sv;
            }
            float mloc = s[i][0];
            #pragma unroll
            for (int j = 1; j < 8; j++) mloc = fmaxf(mloc, s[i][j]);
            #pragma unroll
            for (int off = 8; off > 0; off >>= 1)
                mloc = fmaxf(mloc, __shfl_xor_sync(0xffffffffu, mloc, off));
            float mnew = fmaxf(m_i[i], mloc);
            float ci = __expf(m_i[i] - mnew);
            float ps = 0.f;
            #pragma unroll
            for (int j = 0; j < 8; j++) {
                float p = __expf(s[i][j] - mnew);
                s[i][j] = p;
                ps += p;
            }
            #pragma unroll
            for (int off = 8; off > 0; off >>= 1)
                ps += __shfl_xor_sync(0xffffffffu, ps, off);
            l_i[i] = l_i[i] * ci + ps;
            m_i[i] = mnew;
            c_i[i] = ci;
            #pragma unroll
            for (int jj = 0; jj < 4; jj++) o[i][jj] *= ci;
        }

        // stage P
        #pragma unroll
        for (int i = 0; i < 8; i++) {
            float* pr = &Ps[(ty*8 + i) * PS_LD + tx*8];
            *(float4*)(pr)     = make_float4(s[i][0], s[i][1], s[i][2], s[i][3]);
            *(float4*)(pr + 4) = make_float4(s[i][4], s[i][5], s[i][6], s[i][7]);
        }
        __syncthreads();

        // O += P V   (k unrolled by 4, vector loads)
        #pragma unroll 4
        for (int k0 = 0; k0 < 128; k0 += 4) {
            float4 pa[8];
            #pragma unroll
            for (int i = 0; i < 8; i++)
                pa[i] = *(const float4*)&Ps[(ty*8 + i) * PS_LD + k0];
            #pragma unroll
            for (int t = 0; t < 4; t++) {
                float4 vv = *(const float4*)&Vs[(k0 + t) * VS_LD + tx*4];
                #pragma unroll
                for (int i = 0; i < 8; i++) {
                    float pv = (t == 0) ? pa[i].x : (t == 1) ? pa[i].y
                             : (t == 2) ? pa[i].z : pa[i].w;
                    o[i][0] = fmaf(pv, vv.x, o[i][0]);
                    o[i][1] = fmaf(pv, vv.y, o[i][1]);
                    o[i][2] = fmaf(pv, vv.z, o[i][2]);
                    o[i][3] = fmaf(pv, vv.w, o[i][3]);
                }
            }
        }
    }

    #pragma unroll
    for (int i = 0; i < 8; i++) {
        const float invl = 1.0f / l_i[i];
        const size_t t = (size_t)(b * TT + qb * 128 + ty * 8 + i);
        *(float4*)(g_ao + t * DMODEL + h * HD + tx * 4) =
            make_float4(o[i][0]*invl, o[i][1]*invl, o[i][2]*invl, o[i][3]*invl);
    }
}

// ---------------------------------------------------------------------------
// Kernel C: output projection  out = g_ao @ wo. Same 128x128x8 SGEMM.
// grid = (NTOK/128, DM/128)
// ---------------------------------------------------------------------------
__global__ __launch_bounds__(256) void out_kernel(
    const float* __restrict__ wo, float* __restrict__ out)
{
    __shared__ float As[2][8][132];
    __shared__ float Bs[2][8][132];

    const int tid = threadIdx.x;
    const int tx = tid & 15, ty = tid >> 4;
    const int m0 = blockIdx.x * 128, n0 = blockIdx.y * 128;

    const int am = tid >> 1, ak = (tid & 1) * 4;
    const int bk = tid >> 5, bn = (tid & 31) * 4;

    float acc[8][8] = {};

    float4 a4 = *(const float4*)(g_ao + (size_t)(m0 + am) * DMODEL + ak);
    float4 b4 = *(const float4*)(wo + (size_t)bk * DMODEL + n0 + bn);
    As[0][ak+0][am] = a4.x; As[0][ak+1][am] = a4.y;
    As[0][ak+2][am] = a4.z; As[0][ak+3][am] = a4.w;
    *(float4*)&Bs[0][bk][bn] = b4;
    __syncthreads();

    int buf = 0;
    for (int k0 = 0; k0 < DMODEL; k0 += 8) {
        const bool more = (k0 + 8 < DMODEL);
        if (more) {
            a4 = *(const float4*)(g_ao + (size_t)(m0 + am) * DMODEL + k0 + 8 + ak);
            b4 = *(const float4*)(wo + (size_t)(k0 + 8 + bk) * DMODEL + n0 + bn);
        }
        #pragma unroll
        for (int kk = 0; kk < 8; kk++) {
            float a[8], b[8];
            *(float4*)(a)     = *(const float4*)&As[buf][kk][ty*8];
            *(float4*)(a + 4) = *(const float4*)&As[buf][kk][ty*8 + 4];
            *(float4*)(b)     = *(const float4*)&Bs[buf][kk][tx*8];
            *(float4*)(b + 4) = *(const float4*)&Bs[buf][kk][tx*8 + 4];
            #pragma unroll
            for (int i = 0; i < 8; i++)
                #pragma unroll
                for (int j = 0; j < 8; j++)
                    acc[i][j] = fmaf(a[i], b[j], acc[i][j]);
        }
        if (more) {
            As[buf^1][ak+0][am] = a4.x; As[buf^1][ak+1][am] = a4.y;
            As[buf^1][ak+2][am] = a4.z; As[buf^1][ak+3][am] = a4.w;
            *(float4*)&Bs[buf^1][bk][bn] = b4;
            __syncthreads();
            buf ^= 1;
        }
    }

    #pragma unroll
    for (int i = 0; i < 8; i++) {
        float* dst = out + (size_t)(m0 + ty*8 + i) * DMODEL + n0 + tx*8;
        *(float4*)(dst)     = make_float4(acc[i][0], acc[i][1], acc[i][2], acc[i][3]);
        *(float4*)(dst + 4) = make_float4(acc[i][4], acc[i][5], acc[i][6], acc[i][7]);
    }
}

// ---------------------------------------------------------------------------
extern "C" void kernel_launch(void* const* d_in, const int* in_sizes, int n_in,
                              void* d_out, int out_size) {
    const float* x    = (const float*)d_in[0];
    const float* cosb = (const float*)d_in[1];
    const float* sinb = (const float*)d_in[2];
    const float* wq   = (const float*)d_in[3];
    const float* wk   = (const float*)d_in[4];
    const float* wv   = (const float*)d_in[5];
    const float* wo   = (const float*)d_in[6];
    const float* qn_w = (const float*)d_in[7];
    const float* kn_w = (const float*)d_in[8];
    float* out = (float*)d_out;

    static int smem_set = 0;
    if (!smem_set) {
        cudaFuncSetAttribute(attn_kernel,
                             cudaFuncAttributeMaxDynamicSharedMemorySize, SM_TOTAL);
        smem_set = 1;
    }

    dim3 gA(NTOK / 128, 12);
    qkv_kernel<<<gA, 256>>>(x, wq, wk, wv, cosb, sinb, qn_w, kn_w);

    dim3 gB(TT / 128, BB * NH);
    attn_kernel<<<gB, 256, SM_TOTAL>>>();

    dim3 gC(NTOK / 128, DMODEL / 128);
    out_kernel<<<gC, 256>>>(wo, out);
}

// round 3
// speedup vs baseline: 3.0157x; 2.1530x over previous
#include <cuda_runtime.h>
#include <cuda_bf16.h>
#include <math.h>
#include <stdint.h>

#define BB 2
#define TT 2048
#define NH 16
#define NKV 4
#define HD 64
#define DMODEL 1024
#define NTOK (BB*TT)

// Scratch (device globals; allocation-free per harness rules)
__device__ float g_q[(size_t)BB*NH*TT*HD];    // [B,H,T,D]
__device__ float g_k[(size_t)BB*NKV*TT*HD];   // [B,KV,T,D]
__device__ float g_v[(size_t)BB*NKV*TT*HD];   // [B,KV,T,D]
__device__ float g_ao[(size_t)NTOK*DMODEL];   // [B*T, H*D]

// ---------------------------------------------------------------------------
// helpers
// ---------------------------------------------------------------------------
__device__ __forceinline__ uint32_t sptr(const void* p) {
    return (uint32_t)__cvta_generic_to_shared(p);
}
__device__ __forceinline__ void ldsm4(uint32_t* r, uint32_t a) {
    asm volatile("ldmatrix.sync.aligned.m8n8.x4.shared.b16 {%0,%1,%2,%3},[%4];"
        : "=r"(r[0]), "=r"(r[1]), "=r"(r[2]), "=r"(r[3]) : "r"(a));
}
__device__ __forceinline__ void ldsm4t(uint32_t* r, uint32_t a) {
    asm volatile("ldmatrix.sync.aligned.m8n8.x4.trans.shared.b16 {%0,%1,%2,%3},[%4];"
        : "=r"(r[0]), "=r"(r[1]), "=r"(r[2]), "=r"(r[3]) : "r"(a));
}
__device__ __forceinline__ void mma16816(float* c, const uint32_t* a,
                                          uint32_t b0, uint32_t b1) {
    asm volatile("mma.sync.aligned.m16n8k16.row.col.f32.bf16.bf16.f32 "
        "{%0,%1,%2,%3},{%4,%5,%6,%7},{%8,%9},{%0,%1,%2,%3};"
        : "+f"(c[0]), "+f"(c[1]), "+f"(c[2]), "+f"(c[3])
        : "r"(a[0]), "r"(a[1]), "r"(a[2]), "r"(a[3]), "r"(b0), "r"(b1));
}
__device__ __forceinline__ uint32_t pkbf(__nv_bfloat16 a, __nv_bfloat16 b) {
    return (uint32_t)__bfloat16_as_ushort(a) |
           ((uint32_t)__bfloat16_as_ushort(b) << 16);
}
// convert 4 floats to hi/lo bf16 and store (2x uint32 each)
__device__ __forceinline__ void cvt_hilo4(float4 v, __nv_bfloat16* hp, __nv_bfloat16* lp) {
    __nv_bfloat16 h0 = __float2bfloat16(v.x), h1 = __float2bfloat16(v.y);
    __nv_bfloat16 h2 = __float2bfloat16(v.z), h3 = __float2bfloat16(v.w);
    __nv_bfloat16 l0 = __float2bfloat16(v.x - __bfloat162float(h0));
    __nv_bfloat16 l1 = __float2bfloat16(v.y - __bfloat162float(h1));
    __nv_bfloat16 l2 = __float2bfloat16(v.z - __bfloat162float(h2));
    __nv_bfloat16 l3 = __float2bfloat16(v.w - __bfloat162float(h3));
    ((uint32_t*)hp)[0] = pkbf(h0, h1); ((uint32_t*)hp)[1] = pkbf(h2, h3);
    ((uint32_t*)lp)[0] = pkbf(l0, l1); ((uint32_t*)lp)[1] = pkbf(l2, l3);
}

// GEMM smem element offsets (bf16 units)
#define GEMM_AH 0
#define GEMM_AL 8192          // 2*128*32
#define GEMM_BH 16384
#define GEMM_BL 25088         // + 2*32*136
#define GEMM_SMEM_BYTES 67584 // 33792 elems * 2

// ---------------------------------------------------------------------------
// Kernel A: QKV projection via bf16-split tensor core MMA + RMSNorm/RoPE.
// block 128x128, 8 warps each m16 x n128. grid=(NTOK/128, 12)
// ---------------------------------------------------------------------------
__global__ __launch_bounds__(256) void qkv_kernel(
    const float* __restrict__ x,  const float* __restrict__ wq,
    const float* __restrict__ wk, const float* __restrict__ wv,
    const float* __restrict__ cosb, const float* __restrict__ sinb,
    const float* __restrict__ qn_w, const float* __restrict__ kn_w)
{
    extern __shared__ __nv_bfloat16 smg[];
    __nv_bfloat16* Ah = smg + GEMM_AH;  // [2][128][32]
    __nv_bfloat16* Al = smg + GEMM_AL;
    __nv_bfloat16* Bh = smg + GEMM_BH;  // [2][32][136]
    __nv_bfloat16* Bl = smg + GEMM_BL;

    const int tid = threadIdx.x, ln = tid & 31, wid = tid >> 5;
    const int m0 = blockIdx.x * 128;
    const int nblk = blockIdx.y;

    const float* W; int ldw, kind, n0w;
    if (nblk < 8)       { W = wq; ldw = 1024; n0w = nblk * 128;        kind = 0; }
    else if (nblk < 10) { W = wk; ldw = 256;  n0w = (nblk - 8) * 128;  kind = 1; }
    else                { W = wv; ldw = 256;  n0w = (nblk - 10) * 128; kind = 2; }

    const int mrow = wid * 16;
    float s[16][4] = {};

    // preload chunk 0
    #pragma unroll
    for (int it = 0; it < 4; it++) {
        int u = it * 256 + tid; int r = u >> 3, c = (u & 7) << 2;
        float4 v = *(const float4*)(x + (size_t)(m0 + r) * DMODEL + c);
        cvt_hilo4(v, Ah + r * 32 + c, Al + r * 32 + c);
    }
    #pragma unroll
    for (int it = 0; it < 4; it++) {
        int u = it * 256 + tid; int r = u >> 5, c = (u & 31) << 2;
        float4 v = *(const float4*)(W + (size_t)r * ldw + n0w + c);
        cvt_hilo4(v, Bh + r * 136 + c, Bl + r * 136 + c);
    }
    __syncthreads();

    int buf = 0;
    for (int k0 = 0; k0 < DMODEL; k0 += 32) {
        const bool more = (k0 + 32 < DMODEL);
        float4 pa[4], pb[4];
        if (more) {
            #pragma unroll
            for (int it = 0; it < 4; it++) {
                int u = it * 256 + tid; int r = u >> 3, c = (u & 7) << 2;
                pa[it] = *(const float4*)(x + (size_t)(m0 + r) * DMODEL + k0 + 32 + c);
            }
            #pragma unroll
            for (int it = 0; it < 4; it++) {
                int u = it * 256 + tid; int r = u >> 5, c = (u & 31) << 2;
                pb[it] = *(const float4*)(W + (size_t)(k0 + 32 + r) * ldw + n0w + c);
            }
        }
        const __nv_bfloat16* ah_ = Ah + buf * 4096;
        const __nv_bfloat16* al_ = Al + buf * 4096;
        const __nv_bfloat16* bh_ = Bh + buf * 4352;
        const __nv_bfloat16* bl_ = Bl + buf * 4352;

        #pragma unroll
        for (int kk = 0; kk < 2; kk++) {
            uint32_t ah4[4], al4[4];
            const int acol = kk * 16 + ((ln >> 4) << 3);
            ldsm4(ah4, sptr(ah_ + (mrow + (ln & 15)) * 32 + acol));
            ldsm4(al4, sptr(al_ + (mrow + (ln & 15)) * 32 + acol));
            #pragma unroll
            for (int np = 0; np < 8; np++) {
                const int brow = kk * 16 + (ln & 7) + (((ln >> 3) & 1) << 3);
                const int bcol = np * 16 + ((ln >> 4) << 3);
                uint32_t bh4[4], bl4[4];
                ldsm4t(bh4, sptr(bh_ + brow * 136 + bcol));
                ldsm4t(bl4, sptr(bl_ + brow * 136 + bcol));
                mma16816(s[2*np],   ah4, bh4[0], bh4[1]);
                mma16816(s[2*np],   al4, bh4[0], bh4[1]);
                mma16816(s[2*np],   ah4, bl4[0], bl4[1]);
                mma16816(s[2*np+1], ah4, bh4[2], bh4[3]);
                mma16816(s[2*np+1], al4, bh4[2], bh4[3]);
                mma16816(s[2*np+1], ah4, bl4[2], bl4[3]);
            }
        }
        if (more) {
            __nv_bfloat16* ahn = Ah + (buf ^ 1) * 4096;
            __nv_bfloat16* aln = Al + (buf ^ 1) * 4096;
            __nv_bfloat16* bhn = Bh + (buf ^ 1) * 4352;
            __nv_bfloat16* bln = Bl + (buf ^ 1) * 4352;
            #pragma unroll
            for (int it = 0; it < 4; it++) {
                int u = it * 256 + tid; int r = u >> 3, c = (u & 7) << 2;
                cvt_hilo4(pa[it], ahn + r * 32 + c, aln + r * 32 + c);
            }
            #pragma unroll
            for (int it = 0; it < 4; it++) {
                int u = it * 256 + tid; int r = u >> 5, c = (u & 31) << 2;
                cvt_hilo4(pb[it], bhn + r * 136 + c, bln + r * 136 + c);
            }
            __syncthreads();
            buf ^= 1;
        }
    }

    // epilogue: RMSNorm + RoPE (Q/K only), store to [B,H,T,D]
    const int q2 = (ln & 3) * 2;
    #pragma unroll
    for (int hf = 0; hf < 2; hf++) {
        const int row = m0 + mrow + (ln >> 2) + hf * 8;
        const int b = row >> 11, tpos = row & 2047;
        if (kind != 2) {
            const float* nw = (kind == 0) ? qn_w : kn_w;
            #pragma unroll
            for (int hh = 0; hh < 2; hh++) {
                const int fb = hh * 8;
                float ss = 0.f;
                #pragma unroll
                for (int f = 0; f < 8; f++) {
                    float v0 = s[fb+f][hf*2], v1 = s[fb+f][hf*2+1];
                    ss = fmaf(v0, v0, fmaf(v1, v1, ss));
                }
                ss += __shfl_xor_sync(0xffffffffu, ss, 1);
                ss += __shfl_xor_sync(0xffffffffu, ss, 2);
                const float inv = rsqrtf(ss * (1.f/64.f) + 1e-6f);
                #pragma unroll
                for (int j2 = 0; j2 < 4; j2++) {
                    #pragma unroll
                    for (int e = 0; e < 2; e++) {
                        const int hc = 8*j2 + q2 + e;   // 0..31
                        const int p = hf*2 + e;
                        float v1 = s[fb+j2][p]   * inv * nw[hc];
                        float v2 = s[fb+j2+4][p] * inv * nw[hc+32];
                        float cc = cosb[tpos*32 + hc], sn = sinb[tpos*32 + hc];
                        s[fb+j2][p]   = v1*cc - v2*sn;
                        s[fb+j2+4][p] = v2*cc + v1*sn;
                    }
                }
            }
        }
        #pragma unroll
        for (int f = 0; f < 16; f++) {
            const int col = 8*f + q2;
            const int hl = col >> 6, d = col & 63;
            float2 val = make_float2(s[f][hf*2], s[f][hf*2+1]);
            float* dst;
            if (kind == 0) {
                int h = nblk*2 + hl;
                dst = g_q + (((size_t)(b*NH + h))*TT + tpos)*HD + d;
            } else if (kind == 1) {
                int h = (nblk-8)*2 + hl;
                dst = g_k + (((size_t)(b*NKV + h))*TT + tpos)*HD + d;
            } else {
                int h = (nblk-10)*2 + hl;
                dst = g_v + (((size_t)(b*NKV + h))*TT + tpos)*HD + d;
            }
            *(float2*)dst = val;
        }
    }
}

// ---------------------------------------------------------------------------
// Kernel B: causal flash attention, bf16-split MMA, P kept in registers.
// grid=(T/128, B*H), 256 threads. smem: Q/K/V hi+lo, 128x72 bf16 each.
// ---------------------------------------------------------------------------
#define ALDT 72
#define ATTN_SMEM_BYTES (6*128*ALDT*2)

__global__ __launch_bounds__(256) void attn_kernel()
{
    extern __shared__ __nv_bfloat16 smb[];
    __nv_bfloat16* Qh = smb;
    __nv_bfloat16* Ql = Qh + 128*ALDT;
    __nv_bfloat16* Kh = Ql + 128*ALDT;
    __nv_bfloat16* Kl = Kh + 128*ALDT;
    __nv_bfloat16* Vh = Kl + 128*ALDT;
    __nv_bfloat16* Vl = Vh + 128*ALDT;

    const int tid = threadIdx.x, ln = tid & 31, wid = tid >> 5;
    const int qb = gridDim.x - 1 - blockIdx.x;   // heavy blocks first
    const int bh = blockIdx.y;
    const int b = bh >> 4, h = bh & 15, kvh = h >> 2;

    const float* Qg = g_q + ((size_t)(b*NH + h)*TT + qb*128)*HD;
    const float* Kg = g_k + (size_t)(b*NKV + kvh)*TT*HD;
    const float* Vg = g_v + (size_t)(b*NKV + kvh)*TT*HD;

    #pragma unroll
    for (int it = 0; it < 8; it++) {
        int u = it * 256 + tid; int r = u >> 4, c = (u & 15) << 2;
        float4 v = *(const float4*)(Qg + (size_t)r * HD + c);
        cvt_hilo4(v, Qh + r*ALDT + c, Ql + r*ALDT + c);
    }

    const int mrow = wid * 16;
    const int q2 = (ln & 3) * 2;
    float o[8][4] = {};
    float m_i[2] = {-1e30f, -1e30f}, l_i[2] = {0.f, 0.f};

    for (int kb = 0; kb <= qb; kb++) {
        __syncthreads();  // prior iter done reading K/V (also fences Q store)
        #pragma unroll
        for (int it = 0; it < 8; it++) {
            int u = it * 256 + tid; int r = u >> 4, c = (u & 15) << 2;
            float4 kv = *(const float4*)(Kg + (size_t)(kb*128 + r)*HD + c);
            cvt_hilo4(kv, Kh + r*ALDT + c, Kl + r*ALDT + c);
            float4 vv = *(const float4*)(Vg + (size_t)(kb*128 + r)*HD + c);
            cvt_hilo4(vv, Vh + r*ALDT + c, Vl + r*ALDT + c);
        }
        __syncthreads();

        // S = Q K^T
        float s[16][4];
        #pragma unroll
        for (int f = 0; f < 16; f++) { s[f][0]=0.f; s[f][1]=0.f; s[f][2]=0.f; s[f][3]=0.f; }

        #pragma unroll
        for (int kk = 0; kk < 4; kk++) {
            uint32_t ah4[4], al4[4];
            const int acol = kk * 16 + ((ln >> 4) << 3);
            ldsm4(ah4, sptr(Qh + (mrow + (ln & 15))*ALDT + acol));
            ldsm4(al4, sptr(Ql + (mrow + (ln & 15))*ALDT + acol));
            #pragma unroll
            for (int np = 0; np < 8; np++) {
                const int krow = np*16 + (ln & 7) + ((ln >> 4) << 3);
                const int kcol = kk*16 + (((ln >> 3) & 1) << 3);
                uint32_t bh4[4], bl4[4];
                ldsm4(bh4, sptr(Kh + krow*ALDT + kcol));
                ldsm4(bl4, sptr(Kl + krow*ALDT + kcol));
                mma16816(s[2*np],   ah4, bh4[0], bh4[1]);
                mma16816(s[2*np],   al4, bh4[0], bh4[1]);
                mma16816(s[2*np],   ah4, bl4[0], bl4[1]);
                mma16816(s[2*np+1], ah4, bh4[2], bh4[3]);
                mma16816(s[2*np+1], al4, bh4[2], bh4[3]);
                mma16816(s[2*np+1], ah4, bl4[2], bl4[3]);
            }
        }

        // scale + causal mask
        const bool diag = (kb == qb);
        #pragma unroll
        for (int f = 0; f < 16; f++) {
            #pragma unroll
            for (int p = 0; p < 4; p++) {
                float sv = s[f][p] * 0.125f;
                if (diag) {
                    int ck = 8*f + q2 + (p & 1);
                    int rq = mrow + (ln >> 2) + (p >> 1)*8;
                    if (ck > rq) sv = -1e30f;
                }
                s[f][p] = sv;
            }
        }

        // online softmax (2 rows per thread)
        float ci[2];
        #pragma unroll
        for (int hf = 0; hf < 2; hf++) {
            float mx = -1e30f;
            #pragma unroll
            for (int f = 0; f < 16; f++)
                mx = fmaxf(mx, fmaxf(s[f][hf*2], s[f][hf*2+1]));
            mx = fmaxf(mx, __shfl_xor_sync(0xffffffffu, mx, 1));
            mx = fmaxf(mx, __shfl_xor_sync(0xffffffffu, mx, 2));
            float mnew = fmaxf(m_i[hf], mx);
            float c = __expf(m_i[hf] - mnew);
            float ps = 0.f;
            #pragma unroll
            for (int f = 0; f < 16; f++) {
                float p0 = __expf(s[f][hf*2]   - mnew);
                float p1 = __expf(s[f][hf*2+1] - mnew);
                s[f][hf*2] = p0; s[f][hf*2+1] = p1;
                ps += p0 + p1;
            }
            ps += __shfl_xor_sync(0xffffffffu, ps, 1);
            ps += __shfl_xor_sync(0xffffffffu, ps, 2);
            l_i[hf] = l_i[hf]*c + ps;
            m_i[hf] = mnew;
            ci[hf] = c;
        }
        #pragma unroll
        for (int f = 0; f < 8; f++) {
            o[f][0] *= ci[0]; o[f][1] *= ci[0];
            o[f][2] *= ci[1]; o[f][3] *= ci[1];
        }

        // O += P V  (P converted in registers: C-frag -> A-frag identity)
        #pragma unroll
        for (int jj = 0; jj < 8; jj++) {
            uint32_t ph[4], pl[4];
            #pragma unroll
            for (int t = 0; t < 4; t++) {
                const float* src = (t < 2) ? s[2*jj] : s[2*jj+1];
                float v0 = src[(t & 1)*2], v1 = src[(t & 1)*2 + 1];
                __nv_bfloat16 h0 = __float2bfloat16(v0), h1 = __float2bfloat16(v1);
                ph[t] = pkbf(h0, h1);
                pl[t] = pkbf(__float2bfloat16(v0 - __bfloat162float(h0)),
                             __float2bfloat16(v1 - __bfloat162float(h1)));
            }
            #pragma unroll
            for (int dp = 0; dp < 4; dp++) {
                const int vrow = jj*16 + (ln & 7) + (((ln >> 3) & 1) << 3);
                const int vcol = dp*16 + ((ln >> 4) << 3);
                uint32_t vh4[4], vl4[4];
                ldsm4t(vh4, sptr(Vh + vrow*ALDT + vcol));
                ldsm4t(vl4, sptr(Vl + vrow*ALDT + vcol));
                mma16816(o[2*dp],   ph, vh4[0], vh4[1]);
                mma16816(o[2*dp],   pl, vh4[0], vh4[1]);
                mma16816(o[2*dp],   ph, vl4[0], vl4[1]);
                mma16816(o[2*dp+1], ph, vh4[2], vh4[3]);
                mma16816(o[2*dp+1], pl, vh4[2], vh4[3]);
                mma16816(o[2*dp+1], ph, vl4[2], vl4[3]);
            }
        }
    }

    #pragma unroll
    for (int hf = 0; hf < 2; hf++) {
        const float inv = 1.0f / l_i[hf];
        const int row = qb*128 + mrow + (ln >> 2) + hf*8;
        const size_t t = (size_t)(b*TT + row);
        #pragma unroll
        for (int f = 0; f < 8; f++) {
            const int d = 8*f + q2;
            *(float2*)(g_ao + t*DMODEL + h*HD + d) =
                make_float2(o[f][hf*2]*inv, o[f][hf*2+1]*inv);
        }
    }
}

// ---------------------------------------------------------------------------
// Kernel C: output projection via bf16-split MMA. grid=(NTOK/128, DM/128)
// ---------------------------------------------------------------------------
__global__ __launch_bounds__(256) void out_kernel(
    const float* __restrict__ wo, float* __restrict__ out)
{
    extern __shared__ __nv_bfloat16 smg[];
    __nv_bfloat16* Ah = smg + GEMM_AH;
    __nv_bfloat16* Al = smg + GEMM_AL;
    __nv_bfloat16* Bh = smg + GEMM_BH;
    __nv_bfloat16* Bl = smg + GEMM_BL;

    const int tid = threadIdx.x, ln = tid & 31, wid = tid >> 5;
    const int m0 = blockIdx.x * 128, n0 = blockIdx.y * 128;
    const int mrow = wid * 16;
    float s[16][4] = {};

    #pragma unroll
    for (int it = 0; it < 4; it++) {
        int u = it * 256 + tid; int r = u >> 3, c = (u & 7) << 2;
        float4 v = *(const float4*)(g_ao + (size_t)(m0 + r)*DMODEL + c);
        cvt_hilo4(v, Ah + r*32 + c, Al + r*32 + c);
    }
    #pragma unroll
    for (int it = 0; it < 4; it++) {
        int u = it * 256 + tid; int r = u >> 5, c = (u & 31) << 2;
        float4 v = *(const float4*)(wo + (size_t)r*DMODEL + n0 + c);
        cvt_hilo4(v, Bh + r*136 + c, Bl + r*136 + c);
    }
    __syncthreads();

    int buf = 0;
    for (int k0 = 0; k0 < DMODEL; k0 += 32) {
        const bool more = (k0 + 32 < DMODEL);
        float4 pa[4], pb[4];
        if (more) {
            #pragma unroll
            for (int it = 0; it < 4; it++) {
                int u = it * 256 + tid; int r = u >> 3, c = (u & 7) << 2;
                pa[it] = *(const float4*)(g_ao + (size_t)(m0 + r)*DMODEL + k0 + 32 + c);
            }
            #pragma unroll
            for (int it = 0; it < 4; it++) {
                int u = it * 256 + tid; int r = u >> 5, c = (u & 31) << 2;
                pb[it] = *(const float4*)(wo + (size_t)(k0 + 32 + r)*DMODEL + n0 + c);
            }
        }
        const __nv_bfloat16* ah_ = Ah + buf*4096;
        const __nv_bfloat16* al_ = Al + buf*4096;
        const __nv_bfloat16* bh_ = Bh + buf*4352;
        const __nv_bfloat16* bl_ = Bl + buf*4352;

        #pragma unroll
        for (int kk = 0; kk < 2; kk++) {
            uint32_t ah4[4], al4[4];
            const int acol = kk*16 + ((ln >> 4) << 3);
            ldsm4(ah4, sptr(ah_ + (mrow + (ln & 15))*32 + acol));
            ldsm4(al4, sptr(al_ + (mrow + (ln & 15))*32 + acol));
            #pragma unroll
            for (int np = 0; np < 8; np++) {
                const int brow = kk*16 + (ln & 7) + (((ln >> 3) & 1) << 3);
                const int bcol = np*16 + ((ln >> 4) << 3);
                uint32_t bh4[4], bl4[4];
                ldsm4t(bh4, sptr(bh_ + brow*136 + bcol));
                ldsm4t(bl4, sptr(bl_ + brow*136 + bcol));
                mma16816(s[2*np],   ah4, bh4[0], bh4[1]);
                mma16816(s[2*np],   al4, bh4[0], bh4[1]);
                mma16816(s[2*np],   ah4, bl4[0], bl4[1]);
                mma16816(s[2*np+1], ah4, bh4[2], bh4[3]);
                mma16816(s[2*np+1], al4, bh4[2], bh4[3]);
                mma16816(s[2*np+1], ah4, bl4[2], bl4[3]);
            }
        }
        if (more) {
            __nv_bfloat16* ahn = Ah + (buf^1)*4096;
            __nv_bfloat16* aln = Al + (buf^1)*4096;
            __nv_bfloat16* bhn = Bh + (buf^1)*4352;
            __nv_bfloat16* bln = Bl + (buf^1)*4352;
            #pragma unroll
            for (int it = 0; it < 4; it++) {
                int u = it * 256 + tid; int r = u >> 3, c = (u & 7) << 2;
                cvt_hilo4(pa[it], ahn + r*32 + c, aln + r*32 + c);
            }
            #pragma unroll
            for (int it = 0; it < 4; it++) {
                int u = it * 256 + tid; int r = u >> 5, c = (u & 31) << 2;
                cvt_hilo4(pb[it], bhn + r*136 + c, bln + r*136 + c);
            }
            __syncthreads();
            buf ^= 1;
        }
    }

    const int q2 = (ln & 3) * 2;
    #pragma unroll
    for (int hf = 0; hf < 2; hf++) {
        const int row = m0 + mrow + (ln >> 2) + hf*8;
        #pragma unroll
        for (int f = 0; f < 16; f++) {
            const int col = n0 + 8*f + q2;
            *(float2*)(out + (size_t)row*DMODEL + col) =
                make_float2(s[f][hf*2], s[f][hf*2+1]);
        }
    }
}

// ---------------------------------------------------------------------------
extern "C" void kernel_launch(void* const* d_in, const int* in_sizes, int n_in,
                              void* d_out, int out_size) {
    const float* x    = (const float*)d_in[0];
    const float* cosb = (const float*)d_in[1];
    const float* sinb = (const float*)d_in[2];
    const float* wq   = (const float*)d_in[3];
    const float* wk   = (const float*)d_in[4];
    const float* wv   = (const float*)d_in[5];
    const float* wo   = (const float*)d_in[6];
    const float* qn_w = (const float*)d_in[7];
    const float* kn_w = (const float*)d_in[8];
    float* out = (float*)d_out;

    static int smem_set = 0;
    if (!smem_set) {
        cudaFuncSetAttribute(qkv_kernel,
            cudaFuncAttributeMaxDynamicSharedMemorySize, GEMM_SMEM_BYTES);
        cudaFuncSetAttribute(attn_kernel,
            cudaFuncAttributeMaxDynamicSharedMemorySize, ATTN_SMEM_BYTES);
        cudaFuncSetAttribute(out_kernel,
            cudaFuncAttributeMaxDynamicSharedMemorySize, GEMM_SMEM_BYTES);
        smem_set = 1;
    }

    dim3 gA(NTOK / 128, 12);
    qkv_kernel<<<gA, 256, GEMM_SMEM_BYTES>>>(x, wq, wk, wv, cosb, sinb, qn_w, kn_w);

    dim3 gB(TT / 128, BB * NH);
    attn_kernel<<<gB, 256, ATTN_SMEM_BYTES>>>();

    dim3 gC(NTOK / 128, DMODEL / 128);
    out_kernel<<<gC, 256, GEMM_SMEM_BYTES>>>(wo, out);
}

// round 4
// speedup vs baseline: 3.6352x; 1.2054x over previous
#include <cuda_runtime.h>
#include <cuda_bf16.h>
#include <math.h>
#include <stdint.h>

#define BB 2
#define TT 2048
#define NH 16
#define NKV 4
#define HD 64
#define DMODEL 1024
#define NTOK (BB*TT)

// ---------------- precomputed bf16 hi/lo operands (device globals) ----------
__device__ __nv_bfloat16 g_xh[(size_t)NTOK*DMODEL],  g_xl[(size_t)NTOK*DMODEL];
__device__ __nv_bfloat16 g_wqh[(size_t)DMODEL*NH*HD], g_wql[(size_t)DMODEL*NH*HD];
__device__ __nv_bfloat16 g_wkh[(size_t)DMODEL*NKV*HD], g_wkl[(size_t)DMODEL*NKV*HD];
__device__ __nv_bfloat16 g_wvh[(size_t)DMODEL*NKV*HD], g_wvl[(size_t)DMODEL*NKV*HD];
__device__ __nv_bfloat16 g_woh[(size_t)NH*HD*DMODEL], g_wol[(size_t)NH*HD*DMODEL];
// intermediates (bf16 hi/lo)
__device__ __nv_bfloat16 g_qh[(size_t)BB*NH*TT*HD],  g_ql[(size_t)BB*NH*TT*HD];
__device__ __nv_bfloat16 g_kh[(size_t)BB*NKV*TT*HD], g_kl[(size_t)BB*NKV*TT*HD];
__device__ __nv_bfloat16 g_vh[(size_t)BB*NKV*TT*HD], g_vl[(size_t)BB*NKV*TT*HD];
__device__ __nv_bfloat16 g_aoh[(size_t)NTOK*DMODEL], g_aol[(size_t)NTOK*DMODEL];

// ---------------------------------------------------------------------------
// helpers
// ---------------------------------------------------------------------------
__device__ __forceinline__ uint32_t sptr(const void* p) {
    return (uint32_t)__cvta_generic_to_shared(p);
}
__device__ __forceinline__ void ldsm4(uint32_t* r, uint32_t a) {
    asm volatile("ldmatrix.sync.aligned.m8n8.x4.shared.b16 {%0,%1,%2,%3},[%4];"
        : "=r"(r[0]), "=r"(r[1]), "=r"(r[2]), "=r"(r[3]) : "r"(a));
}
__device__ __forceinline__ void ldsm4t(uint32_t* r, uint32_t a) {
    asm volatile("ldmatrix.sync.aligned.m8n8.x4.trans.shared.b16 {%0,%1,%2,%3},[%4];"
        : "=r"(r[0]), "=r"(r[1]), "=r"(r[2]), "=r"(r[3]) : "r"(a));
}
__device__ __forceinline__ void mma16816(float* c, const uint32_t* a,
                                          uint32_t b0, uint32_t b1) {
    asm volatile("mma.sync.aligned.m16n8k16.row.col.f32.bf16.bf16.f32 "
        "{%0,%1,%2,%3},{%4,%5,%6,%7},{%8,%9},{%0,%1,%2,%3};"
        : "+f"(c[0]), "+f"(c[1]), "+f"(c[2]), "+f"(c[3])
        : "r"(a[0]), "r"(a[1]), "r"(a[2]), "r"(a[3]), "r"(b0), "r"(b1));
}
__device__ __forceinline__ uint32_t pkbf(__nv_bfloat16 a, __nv_bfloat16 b) {
    return (uint32_t)__bfloat16_as_ushort(a) |
           ((uint32_t)__bfloat16_as_ushort(b) << 16);
}
__device__ __forceinline__ void cvt_hilo4(float4 v, __nv_bfloat16* hp, __nv_bfloat16* lp) {
    __nv_bfloat16 h0 = __float2bfloat16(v.x), h1 = __float2bfloat16(v.y);
    __nv_bfloat16 h2 = __float2bfloat16(v.z), h3 = __float2bfloat16(v.w);
    __nv_bfloat16 l0 = __float2bfloat16(v.x - __bfloat162float(h0));
    __nv_bfloat16 l1 = __float2bfloat16(v.y - __bfloat162float(h1));
    __nv_bfloat16 l2 = __float2bfloat16(v.z - __bfloat162float(h2));
    __nv_bfloat16 l3 = __float2bfloat16(v.w - __bfloat162float(h3));
    ((uint32_t*)hp)[0] = pkbf(h0, h1); ((uint32_t*)hp)[1] = pkbf(h2, h3);
    ((uint32_t*)lp)[0] = pkbf(l0, l1); ((uint32_t*)lp)[1] = pkbf(l2, l3);
}
__device__ __forceinline__ void cpa16(uint32_t dst, const void* src) {
    asm volatile("cp.async.cg.shared.global [%0],[%1],16;" :: "r"(dst), "l"(src));
}
#define CP_COMMIT asm volatile("cp.async.commit_group;")
#define CP_WAIT0  asm volatile("cp.async.wait_group 0;")

// ---------------------------------------------------------------------------
// convert kernel: fp32 -> bf16 hi/lo into selected global pair
// ---------------------------------------------------------------------------
__global__ __launch_bounds__(256) void cvt_kernel(const float* __restrict__ src,
                                                  int which, int n4) {
    __nv_bfloat16 *hi, *lo;
    switch (which) {
        case 0: hi = g_xh;  lo = g_xl;  break;
        case 1: hi = g_wqh; lo = g_wql; break;
        case 2: hi = g_wkh; lo = g_wkl; break;
        case 3: hi = g_wvh; lo = g_wvl; break;
        default: hi = g_woh; lo = g_wol; break;
    }
    for (int i = blockIdx.x * 256 + threadIdx.x; i < n4; i += gridDim.x * 256) {
        float4 v = ((const float4*)src)[i];
        cvt_hilo4(v, hi + (size_t)i * 4, lo + (size_t)i * 4);
    }
}

// ---------------------------------------------------------------------------
// GEMM smem geometry (bf16 elems)
// ---------------------------------------------------------------------------
#define GA_LD 72
#define GB_LD 136
#define GA_SZ (128*GA_LD)
#define GB_SZ (32*GB_LD)
#define GBUF  (2*GA_SZ + 2*GB_SZ)       // one buffer: Ah,Al,Bh,Bl
#define GEMM_SMEM_BYTES (2*GBUF*2)      // 108544

__device__ __forceinline__ void gemm_issue(
    uint32_t smbase, int buf,
    const __nv_bfloat16* Ah, const __nv_bfloat16* Al, int lda,
    const __nv_bfloat16* Bh, const __nv_bfloat16* Bl, int ldb, int tid)
{
    uint32_t ab = smbase + (uint32_t)buf * (GBUF * 2);
    #pragma unroll
    for (int it = 0; it < 2; it++) {                 // A: 128 rows x 32 cols
        int u = it * 256 + tid; int r = u >> 2, c = (u & 3) * 8;
        size_t off = (size_t)r * lda + c;
        cpa16(ab + (r * GA_LD + c) * 2, Ah + off);
        cpa16(ab + (GA_SZ + r * GA_LD + c) * 2, Al + off);
    }
    uint32_t bb = ab + 2 * GA_SZ * 2;
    #pragma unroll
    for (int it = 0; it < 2; it++) {                 // B: 32 rows x 128 cols
        int u = it * 256 + tid; int r = u >> 4, c = (u & 15) * 8;
        size_t off = (size_t)r * ldb + c;
        cpa16(bb + (r * GB_LD + c) * 2, Bh + off);
        cpa16(bb + (GB_SZ + r * GB_LD + c) * 2, Bl + off);
    }
}

__device__ __forceinline__ void gemm_compute(
    const __nv_bfloat16* base, int mrow, int ln, float s[16][4])
{
    const __nv_bfloat16* ah_ = base;
    const __nv_bfloat16* al_ = base + GA_SZ;
    const __nv_bfloat16* bh_ = base + 2 * GA_SZ;
    const __nv_bfloat16* bl_ = bh_ + GB_SZ;
    #pragma unroll
    for (int kk = 0; kk < 2; kk++) {
        uint32_t ah4[4], al4[4];
        const int acol = kk * 16 + ((ln >> 4) << 3);
        ldsm4(ah4, sptr(ah_ + (mrow + (ln & 15)) * GA_LD + acol));
        ldsm4(al4, sptr(al_ + (mrow + (ln & 15)) * GA_LD + acol));
        #pragma unroll
        for (int np = 0; np < 8; np++) {
            const int brow = kk * 16 + (ln & 7) + (((ln >> 3) & 1) << 3);
            const int bcol = np * 16 + ((ln >> 4) << 3);
            uint32_t bh4[4], bl4[4];
            ldsm4t(bh4, sptr(bh_ + brow * GB_LD + bcol));
            ldsm4t(bl4, sptr(bl_ + brow * GB_LD + bcol));
            mma16816(s[2*np],   ah4, bh4[0], bh4[1]);
            mma16816(s[2*np],   al4, bh4[0], bh4[1]);
            mma16816(s[2*np],   ah4, bl4[0], bl4[1]);
            mma16816(s[2*np+1], ah4, bh4[2], bh4[3]);
            mma16816(s[2*np+1], al4, bh4[2], bh4[3]);
            mma16816(s[2*np+1], ah4, bl4[2], bl4[3]);
        }
    }
}

// ---------------------------------------------------------------------------
// Kernel A: QKV projection + RMSNorm + RoPE, outputs bf16 hi/lo Q/K/V.
// grid=(NTOK/128, 12)
// ---------------------------------------------------------------------------
__global__ void __launch_bounds__(256, 2) qkv_kernel(
    const float* __restrict__ cosb, const float* __restrict__ sinb,
    const float* __restrict__ qn_w, const float* __restrict__ kn_w)
{
    extern __shared__ __nv_bfloat16 smg[];
    const int tid = threadIdx.x, ln = tid & 31, wid = tid >> 5;
    const int m0 = blockIdx.x * 128;
    const int nblk = blockIdx.y;

    const __nv_bfloat16 *Wh, *Wl; int ldw, kind, n0w;
    if (nblk < 8)       { Wh = g_wqh; Wl = g_wql; ldw = 1024; n0w = nblk * 128;      kind = 0; }
    else if (nblk < 10) { Wh = g_wkh; Wl = g_wkl; ldw = 256;  n0w = (nblk-8) * 128;  kind = 1; }
    else                { Wh = g_wvh; Wl = g_wvl; ldw = 256;  n0w = (nblk-10) * 128; kind = 2; }

    const int mrow = wid * 16;
    const uint32_t smbase = sptr(smg);
    float s[16][4] = {};

    gemm_issue(smbase, 0, g_xh + (size_t)m0 * DMODEL, g_xl + (size_t)m0 * DMODEL, DMODEL,
               Wh + n0w, Wl + n0w, ldw, tid);
    CP_COMMIT;

    int buf = 0;
    for (int k0 = 0; k0 < DMODEL; k0 += 32) {
        CP_WAIT0;
        __syncthreads();
        if (k0 + 32 < DMODEL) {
            gemm_issue(smbase, buf ^ 1,
                       g_xh + (size_t)m0 * DMODEL + k0 + 32,
                       g_xl + (size_t)m0 * DMODEL + k0 + 32, DMODEL,
                       Wh + (size_t)(k0 + 32) * ldw + n0w,
                       Wl + (size_t)(k0 + 32) * ldw + n0w, ldw, tid);
            CP_COMMIT;
        }
        gemm_compute(smg + buf * GBUF, mrow, ln, s);
        buf ^= 1;
    }

    // epilogue: RMSNorm + RoPE (Q/K), store bf16 hi/lo to [B,H,T,D]
    const int q2 = (ln & 3) * 2;
    #pragma unroll
    for (int hf = 0; hf < 2; hf++) {
        const int row = m0 + mrow + (ln >> 2) + hf * 8;
        const int b = row >> 11, tpos = row & 2047;
        if (kind != 2) {
            const float* nw = (kind == 0) ? qn_w : kn_w;
            #pragma unroll
            for (int hh = 0; hh < 2; hh++) {
                const int fb = hh * 8;
                float ss = 0.f;
                #pragma unroll
                for (int f = 0; f < 8; f++) {
                    float v0 = s[fb+f][hf*2], v1 = s[fb+f][hf*2+1];
                    ss = fmaf(v0, v0, fmaf(v1, v1, ss));
                }
                ss += __shfl_xor_sync(0xffffffffu, ss, 1);
                ss += __shfl_xor_sync(0xffffffffu, ss, 2);
                const float inv = rsqrtf(ss * (1.f/64.f) + 1e-6f);
                #pragma unroll
                for (int j2 = 0; j2 < 4; j2++) {
                    #pragma unroll
                    for (int e = 0; e < 2; e++) {
                        const int hc = 8*j2 + q2 + e;
                        const int p = hf*2 + e;
                        float v1 = s[fb+j2][p]   * inv * nw[hc];
                        float v2 = s[fb+j2+4][p] * inv * nw[hc+32];
                        float cc = cosb[tpos*32 + hc], sn = sinb[tpos*32 + hc];
                        s[fb+j2][p]   = v1*cc - v2*sn;
                        s[fb+j2+4][p] = v2*cc + v1*sn;
                    }
                }
            }
        }
        #pragma unroll
        for (int f = 0; f < 16; f++) {
            const int col = 8*f + q2;
            const int hl = col >> 6, d = col & 63;
            float v0 = s[f][hf*2], v1 = s[f][hf*2+1];
            __nv_bfloat16 h0 = __float2bfloat16(v0), h1 = __float2bfloat16(v1);
            uint32_t hiw = pkbf(h0, h1);
            uint32_t low = pkbf(__float2bfloat16(v0 - __bfloat162float(h0)),
                                __float2bfloat16(v1 - __bfloat162float(h1)));
            size_t idx;
            __nv_bfloat16 *dh, *dl;
            if (kind == 0) {
                int h = nblk*2 + hl;
                idx = (((size_t)(b*NH + h))*TT + tpos)*HD + d; dh = g_qh; dl = g_ql;
            } else if (kind == 1) {
                int h = (nblk-8)*2 + hl;
                idx = (((size_t)(b*NKV + h))*TT + tpos)*HD + d; dh = g_kh; dl = g_kl;
            } else {
                int h = (nblk-10)*2 + hl;
                idx = (((size_t)(b*NKV + h))*TT + tpos)*HD + d; dh = g_vh; dl = g_vl;
            }
            *(uint32_t*)(dh + idx) = hiw;
            *(uint32_t*)(dl + idx) = low;
        }
    }
}

// ---------------------------------------------------------------------------
// Kernel B: causal flash attention. Q frags in registers; K/V hi/lo bf16
// double-buffered via cp.async. grid=(T/128, B*H), 256 threads.
// ---------------------------------------------------------------------------
#define ATT_LD 72
#define ATT_ARR (128*ATT_LD)            // 9216 elems
#define ATT_STAGE (4*ATT_ARR)           // Kh,Kl,Vh,Vl
#define ATT_Q_OFF (2*ATT_STAGE)         // Qh,Ql staging
#define ATTN_SMEM_BYTES ((2*ATT_STAGE + 2*ATT_ARR)*2)   // 184320

__device__ __forceinline__ void kv_issue(uint32_t smbase, int stage,
    const __nv_bfloat16* Kh, const __nv_bfloat16* Kl,
    const __nv_bfloat16* Vh, const __nv_bfloat16* Vl, int tid)
{
    uint32_t sb = smbase + (uint32_t)stage * (ATT_STAGE * 2);
    #pragma unroll
    for (int it = 0; it < 4; it++) {      // 1024 chunks per array
        int u = it * 256 + tid; int r = u >> 3, c = (u & 7) * 8;
        size_t off = (size_t)r * HD + c;
        uint32_t d = sb + (r * ATT_LD + c) * 2;
        cpa16(d,                    Kh + off);
        cpa16(d + ATT_ARR*2,        Kl + off);
        cpa16(d + 2*ATT_ARR*2,      Vh + off);
        cpa16(d + 3*ATT_ARR*2,      Vl + off);
    }
}

__global__ void __launch_bounds__(256) attn_kernel()
{
    extern __shared__ __nv_bfloat16 smb[];
    const int tid = threadIdx.x, ln = tid & 31, wid = tid >> 5;
    const int qb = gridDim.x - 1 - blockIdx.x;
    const int bh = blockIdx.y;
    const int b = bh >> 4, h = bh & 15, kvh = h >> 2;
    const uint32_t smbase = sptr(smb);

    const __nv_bfloat16* Qhg = g_qh + ((size_t)(b*NH + h)*TT + qb*128)*HD;
    const __nv_bfloat16* Qlg = g_ql + ((size_t)(b*NH + h)*TT + qb*128)*HD;
    const size_t kvbase = (size_t)(b*NKV + kvh)*TT*HD;

    // prologue: Q + KV stage0 in one cp.async group
    {
        uint32_t qsb = smbase + ATT_Q_OFF * 2;
        #pragma unroll
        for (int it = 0; it < 4; it++) {
            int u = it * 256 + tid; int r = u >> 3, c = (u & 7) * 8;
            size_t off = (size_t)r * HD + c;
            cpa16(qsb + (r * ATT_LD + c) * 2,            Qhg + off);
            cpa16(qsb + (ATT_ARR + r * ATT_LD + c) * 2,  Qlg + off);
        }
    }
    kv_issue(smbase, 0, g_kh + kvbase, g_kl + kvbase, g_vh + kvbase, g_vl + kvbase, tid);
    CP_COMMIT;

    const int mrow = wid * 16;
    const int q2 = (ln & 3) * 2;
    uint32_t qfh[4][4], qfl[4][4];
    float o[8][4] = {};
    float m_i[2] = {-1e30f, -1e30f}, l_i[2] = {0.f, 0.f};

    int buf = 0;
    for (int kb = 0; kb <= qb; kb++) {
        CP_WAIT0;
        __syncthreads();
        if (kb == 0) {
            const __nv_bfloat16* Qh = smb + ATT_Q_OFF;
            const __nv_bfloat16* Ql = Qh + ATT_ARR;
            #pragma unroll
            for (int kk = 0; kk < 4; kk++) {
                const int acol = kk * 16 + ((ln >> 4) << 3);
                ldsm4(qfh[kk], sptr(Qh + (mrow + (ln & 15)) * ATT_LD + acol));
                ldsm4(qfl[kk], sptr(Ql + (mrow + (ln & 15)) * ATT_LD + acol));
            }
        }
        if (kb < qb) {
            size_t o1 = kvbase + (size_t)(kb+1)*128*HD;
            kv_issue(smbase, buf ^ 1, g_kh + o1, g_kl + o1, g_vh + o1, g_vl + o1, tid);
            CP_COMMIT;
        }

        const __nv_bfloat16* Kh = smb + buf * ATT_STAGE;
        const __nv_bfloat16* Kl = Kh + ATT_ARR;
        const __nv_bfloat16* Vh = Kl + ATT_ARR;
        const __nv_bfloat16* Vl = Vh + ATT_ARR;

        // S = Q K^T
        float s[16][4];
        #pragma unroll
        for (int f = 0; f < 16; f++) { s[f][0]=0.f; s[f][1]=0.f; s[f][2]=0.f; s[f][3]=0.f; }
        #pragma unroll
        for (int kk = 0; kk < 4; kk++) {
            #pragma unroll
            for (int np = 0; np < 8; np++) {
                const int krow = np*16 + (ln & 7) + ((ln >> 4) << 3);
                const int kcol = kk*16 + (((ln >> 3) & 1) << 3);
                uint32_t bh4[4], bl4[4];
                ldsm4(bh4, sptr(Kh + krow*ATT_LD + kcol));
                ldsm4(bl4, sptr(Kl + krow*ATT_LD + kcol));
                mma16816(s[2*np],   qfh[kk], bh4[0], bh4[1]);
                mma16816(s[2*np],   qfl[kk], bh4[0], bh4[1]);
                mma16816(s[2*np],   qfh[kk], bl4[0], bl4[1]);
                mma16816(s[2*np+1], qfh[kk], bh4[2], bh4[3]);
                mma16816(s[2*np+1], qfl[kk], bh4[2], bh4[3]);
                mma16816(s[2*np+1], qfh[kk], bl4[2], bl4[3]);
            }
        }

        // scale + causal mask
        const bool diag = (kb == qb);
        #pragma unroll
        for (int f = 0; f < 16; f++) {
            #pragma unroll
            for (int p = 0; p < 4; p++) {
                float sv = s[f][p] * 0.125f;
                if (diag) {
                    int ck = 8*f + q2 + (p & 1);
                    int rq = mrow + (ln >> 2) + (p >> 1)*8;
                    if (ck > rq) sv = -1e30f;
                }
                s[f][p] = sv;
            }
        }

        // online softmax
        float ci[2];
        #pragma unroll
        for (int hf = 0; hf < 2; hf++) {
            float mx = -1e30f;
            #pragma unroll
            for (int f = 0; f < 16; f++)
                mx = fmaxf(mx, fmaxf(s[f][hf*2], s[f][hf*2+1]));
            mx = fmaxf(mx, __shfl_xor_sync(0xffffffffu, mx, 1));
            mx = fmaxf(mx, __shfl_xor_sync(0xffffffffu, mx, 2));
            float mnew = fmaxf(m_i[hf], mx);
            float c = __expf(m_i[hf] - mnew);
            float ps = 0.f;
            #pragma unroll
            for (int f = 0; f < 16; f++) {
                float p0 = __expf(s[f][hf*2]   - mnew);
                float p1 = __expf(s[f][hf*2+1] - mnew);
                s[f][hf*2] = p0; s[f][hf*2+1] = p1;
                ps += p0 + p1;
            }
            ps += __shfl_xor_sync(0xffffffffu, ps, 1);
            ps += __shfl_xor_sync(0xffffffffu, ps, 2);
            l_i[hf] = l_i[hf]*c + ps;
            m_i[hf] = mnew;
            ci[hf] = c;
        }
        #pragma unroll
        for (int f = 0; f < 8; f++) {
            o[f][0] *= ci[0]; o[f][1] *= ci[0];
            o[f][2] *= ci[1]; o[f][3] *= ci[1];
        }

        // O += P V  (P converted in registers)
        #pragma unroll
        for (int jj = 0; jj < 8; jj++) {
            uint32_t ph[4], pl[4];
            #pragma unroll
            for (int t = 0; t < 4; t++) {
                const float* src = (t < 2) ? s[2*jj] : s[2*jj+1];
                float v0 = src[(t & 1)*2], v1 = src[(t & 1)*2 + 1];
                __nv_bfloat16 h0 = __float2bfloat16(v0), h1 = __float2bfloat16(v1);
                ph[t] = pkbf(h0, h1);
                pl[t] = pkbf(__float2bfloat16(v0 - __bfloat162float(h0)),
                             __float2bfloat16(v1 - __bfloat162float(h1)));
            }
            #pragma unroll
            for (int dp = 0; dp < 4; dp++) {
                const int vrow = jj*16 + (ln & 7) + (((ln >> 3) & 1) << 3);
                const int vcol = dp*16 + ((ln >> 4) << 3);
                uint32_t vh4[4], vl4[4];
                ldsm4t(vh4, sptr(Vh + vrow*ATT_LD + vcol));
                ldsm4t(vl4, sptr(Vl + vrow*ATT_LD + vcol));
                mma16816(o[2*dp],   ph, vh4[0], vh4[1]);
                mma16816(o[2*dp],   pl, vh4[0], vh4[1]);
                mma16816(o[2*dp],   ph, vl4[0], vl4[1]);
                mma16816(o[2*dp+1], ph, vh4[2], vh4[3]);
                mma16816(o[2*dp+1], pl, vh4[2], vh4[3]);
                mma16816(o[2*dp+1], ph, vl4[2], vl4[3]);
            }
        }
        buf ^= 1;
    }

    // store O as bf16 hi/lo into g_ao
    #pragma unroll
    for (int hf = 0; hf < 2; hf++) {
        const float inv = 1.0f / l_i[hf];
        const int row = qb*128 + mrow + (ln >> 2) + hf*8;
        const size_t t = (size_t)(b*TT + row);
        #pragma unroll
        for (int f = 0; f < 8; f++) {
            const int d = 8*f + q2;
            float v0 = o[f][hf*2]*inv, v1 = o[f][hf*2+1]*inv;
            __nv_bfloat16 h0 = __float2bfloat16(v0), h1 = __float2bfloat16(v1);
            size_t idx = t*DMODEL + h*HD + d;
            *(uint32_t*)(g_aoh + idx) = pkbf(h0, h1);
            *(uint32_t*)(g_aol + idx) = pkbf(
                __float2bfloat16(v0 - __bfloat162float(h0)),
                __float2bfloat16(v1 - __bfloat162float(h1)));
        }
    }
}

// ---------------------------------------------------------------------------
// Kernel C: output projection. grid=(NTOK/128, DM/128)
// ---------------------------------------------------------------------------
__global__ void __launch_bounds__(256, 2) out_kernel(float* __restrict__ out)
{
    extern __shared__ __nv_bfloat16 smg[];
    const int tid = threadIdx.x, ln = tid & 31, wid = tid >> 5;
    const int m0 = blockIdx.x * 128, n0 = blockIdx.y * 128;
    const int mrow = wid * 16;
    const uint32_t smbase = sptr(smg);
    float s[16][4] = {};

    gemm_issue(smbase, 0, g_aoh + (size_t)m0 * DMODEL, g_aol + (size_t)m0 * DMODEL, DMODEL,
               g_woh + n0, g_wol + n0, DMODEL, tid);
    CP_COMMIT;

    int buf = 0;
    for (int k0 = 0; k0 < DMODEL; k0 += 32) {
        CP_WAIT0;
        __syncthreads();
        if (k0 + 32 < DMODEL) {
            gemm_issue(smbase, buf ^ 1,
                       g_aoh + (size_t)m0 * DMODEL + k0 + 32,
                       g_aol + (size_t)m0 * DMODEL + k0 + 32, DMODEL,
                       g_woh + (size_t)(k0 + 32) * DMODEL + n0,
                       g_wol + (size_t)(k0 + 32) * DMODEL + n0, DMODEL, tid);
            CP_COMMIT;
        }
        gemm_compute(smg + buf * GBUF, mrow, ln, s);
        buf ^= 1;
    }

    const int q2 = (ln & 3) * 2;
    #pragma unroll
    for (int hf = 0; hf < 2; hf++) {
        const int row = m0 + mrow + (ln >> 2) + hf*8;
        #pragma unroll
        for (int f = 0; f < 16; f++) {
            const int col = n0 + 8*f + q2;
            *(float2*)(out + (size_t)row*DMODEL + col) =
                make_float2(s[f][hf*2], s[f][hf*2+1]);
        }
    }
}

// ---------------------------------------------------------------------------
extern "C" void kernel_launch(void* const* d_in, const int* in_sizes, int n_in,
                              void* d_out, int out_size) {
    const float* x    = (const float*)d_in[0];
    const float* cosb = (const float*)d_in[1];
    const float* sinb = (const float*)d_in[2];
    const float* wq   = (const float*)d_in[3];
    const float* wk   = (const float*)d_in[4];
    const float* wv   = (const float*)d_in[5];
    const float* wo   = (const float*)d_in[6];
    const float* qn_w = (const float*)d_in[7];
    const float* kn_w = (const float*)d_in[8];
    float* out = (float*)d_out;

    static int smem_set = 0;
    if (!smem_set) {
        cudaFuncSetAttribute(qkv_kernel,
            cudaFuncAttributeMaxDynamicSharedMemorySize, GEMM_SMEM_BYTES);
        cudaFuncSetAttribute(attn_kernel,
            cudaFuncAttributeMaxDynamicSharedMemorySize, ATTN_SMEM_BYTES);
        cudaFuncSetAttribute(out_kernel,
            cudaFuncAttributeMaxDynamicSharedMemorySize, GEMM_SMEM_BYTES);
        smem_set = 1;
    }

    cvt_kernel<<<2048, 256>>>(x,  0, NTOK*DMODEL/4);
    cvt_kernel<<<1024, 256>>>(wq, 1, DMODEL*NH*HD/4);
    cvt_kernel<<<256,  256>>>(wk, 2, DMODEL*NKV*HD/4);
    cvt_kernel<<<256,  256>>>(wv, 3, DMODEL*NKV*HD/4);
    cvt_kernel<<<1024, 256>>>(wo, 4, NH*HD*DMODEL/4);

    dim3 gA(NTOK / 128, 12);
    qkv_kernel<<<gA, 256, GEMM_SMEM_BYTES>>>(cosb, sinb, qn_w, kn_w);

    dim3 gB(TT / 128, BB * NH);
    attn_kernel<<<gB, 256, ATTN_SMEM_BYTES>>>();

    dim3 gC(NTOK / 128, DMODEL / 128);
    out_kernel<<<gC, 256, GEMM_SMEM_BYTES>>>(out);
}

// round 6
// speedup vs baseline: 3.6485x; 1.0037x over previous
#include <cuda_runtime.h>
#include <cuda_bf16.h>
#include <math.h>
#include <stdint.h>

#define BB 2
#define TT 2048
#define NH 16
#define NKV 4
#define HD 64
#define DMODEL 1024
#define NTOK (BB*TT)

// ---------------- precomputed bf16 hi/lo operands (device globals) ----------
__device__ __nv_bfloat16 g_xh[(size_t)NTOK*DMODEL],  g_xl[(size_t)NTOK*DMODEL];
__device__ __nv_bfloat16 g_wqh[(size_t)DMODEL*NH*HD], g_wql[(size_t)DMODEL*NH*HD];
__device__ __nv_bfloat16 g_wkh[(size_t)DMODEL*NKV*HD], g_wkl[(size_t)DMODEL*NKV*HD];
__device__ __nv_bfloat16 g_wvh[(size_t)DMODEL*NKV*HD], g_wvl[(size_t)DMODEL*NKV*HD];
__device__ __nv_bfloat16 g_woh[(size_t)NH*HD*DMODEL], g_wol[(size_t)NH*HD*DMODEL];
// intermediates (bf16 hi/lo)
__device__ __nv_bfloat16 g_qh[(size_t)BB*NH*TT*HD],  g_ql[(size_t)BB*NH*TT*HD];
__device__ __nv_bfloat16 g_kh[(size_t)BB*NKV*TT*HD], g_kl[(size_t)BB*NKV*TT*HD];
__device__ __nv_bfloat16 g_vh[(size_t)BB*NKV*TT*HD], g_vl[(size_t)BB*NKV*TT*HD];
__device__ __nv_bfloat16 g_aoh[(size_t)NTOK*DMODEL], g_aol[(size_t)NTOK*DMODEL];

// ---------------------------------------------------------------------------
// helpers
// ---------------------------------------------------------------------------
__device__ __forceinline__ uint32_t sptr(const void* p) {
    return (uint32_t)__cvta_generic_to_shared(p);
}
__device__ __forceinline__ void ldsm4(uint32_t* r, uint32_t a) {
    asm volatile("ldmatrix.sync.aligned.m8n8.x4.shared.b16 {%0,%1,%2,%3},[%4];"
        : "=r"(r[0]), "=r"(r[1]), "=r"(r[2]), "=r"(r[3]) : "r"(a));
}
__device__ __forceinline__ void ldsm4t(uint32_t* r, uint32_t a) {
    asm volatile("ldmatrix.sync.aligned.m8n8.x4.trans.shared.b16 {%0,%1,%2,%3},[%4];"
        : "=r"(r[0]), "=r"(r[1]), "=r"(r[2]), "=r"(r[3]) : "r"(a));
}
__device__ __forceinline__ void mma16816(float* c, const uint32_t* a,
                                          uint32_t b0, uint32_t b1) {
    asm volatile("mma.sync.aligned.m16n8k16.row.col.f32.bf16.bf16.f32 "
        "{%0,%1,%2,%3},{%4,%5,%6,%7},{%8,%9},{%0,%1,%2,%3};"
        : "+f"(c[0]), "+f"(c[1]), "+f"(c[2]), "+f"(c[3])
        : "r"(a[0]), "r"(a[1]), "r"(a[2]), "r"(a[3]), "r"(b0), "r"(b1));
}
__device__ __forceinline__ uint32_t pkbf(__nv_bfloat16 a, __nv_bfloat16 b) {
    return (uint32_t)__bfloat16_as_ushort(a) |
           ((uint32_t)__bfloat16_as_ushort(b) << 16);
}
__device__ __forceinline__ void cvt_hilo4(float4 v, __nv_bfloat16* hp, __nv_bfloat16* lp) {
    __nv_bfloat16 h0 = __float2bfloat16(v.x), h1 = __float2bfloat16(v.y);
    __nv_bfloat16 h2 = __float2bfloat16(v.z), h3 = __float2bfloat16(v.w);
    __nv_bfloat16 l0 = __float2bfloat16(v.x - __bfloat162float(h0));
    __nv_bfloat16 l1 = __float2bfloat16(v.y - __bfloat162float(h1));
    __nv_bfloat16 l2 = __float2bfloat16(v.z - __bfloat162float(h2));
    __nv_bfloat16 l3 = __float2bfloat16(v.w - __bfloat162float(h3));
    ((uint32_t*)hp)[0] = pkbf(h0, h1); ((uint32_t*)hp)[1] = pkbf(h2, h3);
    ((uint32_t*)lp)[0] = pkbf(l0, l1); ((uint32_t*)lp)[1] = pkbf(l2, l3);
}
__device__ __forceinline__ void cpa16(uint32_t dst, const void* src) {
    asm volatile("cp.async.cg.shared.global [%0],[%1],16;" :: "r"(dst), "l"(src));
}
#define CP_COMMIT asm volatile("cp.async.commit_group;")
#define CP_WAIT0  asm volatile("cp.async.wait_group 0;")

// ---------------------------------------------------------------------------
// convert kernel: fp32 -> bf16 hi/lo into selected global pair
// ---------------------------------------------------------------------------
__global__ __launch_bounds__(256) void cvt_kernel(const float* __restrict__ src,
                                                  int which, int n4) {
    __nv_bfloat16 *hi, *lo;
    switch (which) {
        case 0: hi = g_xh;  lo = g_xl;  break;
        case 1: hi = g_wqh; lo = g_wql; break;
        case 2: hi = g_wkh; lo = g_wkl; break;
        case 3: hi = g_wvh; lo = g_wvl; break;
        default: hi = g_woh; lo = g_wol; break;
    }
    for (int i = blockIdx.x * 256 + threadIdx.x; i < n4; i += gridDim.x * 256) {
        float4 v = ((const float4*)src)[i];
        cvt_hilo4(v, hi + (size_t)i * 4, lo + (size_t)i * 4);
    }
}

// ---------------------------------------------------------------------------
// GEMM smem geometry (bf16 elems)
// ---------------------------------------------------------------------------
#define GA_LD 72
#define GB_LD 136
#define GA_SZ (128*GA_LD)
#define GB_SZ (32*GB_LD)
#define GBUF  (2*GA_SZ + 2*GB_SZ)       // one buffer: Ah,Al,Bh,Bl
#define GEMM_SMEM_BYTES (2*GBUF*2)      // 108544

__device__ __forceinline__ void gemm_issue(
    uint32_t smbase, int buf,
    const __nv_bfloat16* Ah, const __nv_bfloat16* Al, int lda,
    const __nv_bfloat16* Bh, const __nv_bfloat16* Bl, int ldb, int tid)
{
    uint32_t ab = smbase + (uint32_t)buf * (GBUF * 2);
    #pragma unroll
    for (int it = 0; it < 2; it++) {                 // A: 128 rows x 32 cols
        int u = it * 256 + tid; int r = u >> 2, c = (u & 3) * 8;
        size_t off = (size_t)r * lda + c;
        cpa16(ab + (r * GA_LD + c) * 2, Ah + off);
        cpa16(ab + (GA_SZ + r * GA_LD + c) * 2, Al + off);
    }
    uint32_t bb = ab + 2 * GA_SZ * 2;
    #pragma unroll
    for (int it = 0; it < 2; it++) {                 // B: 32 rows x 128 cols
        int u = it * 256 + tid; int r = u >> 4, c = (u & 15) * 8;
        size_t off = (size_t)r * ldb + c;
        cpa16(bb + (r * GB_LD + c) * 2, Bh + off);
        cpa16(bb + (GB_SZ + r * GB_LD + c) * 2, Bl + off);
    }
}

// 4x2 warp tiling: warp (wy,wx) computes rows [wy*32, wy*32+32) x cols [wx*64, wx*64+64)
__device__ __forceinline__ void gemm_compute(
    const __nv_bfloat16* base, int wy, int wx, int ln, float s[2][8][4])
{
    const __nv_bfloat16* ah_ = base;
    const __nv_bfloat16* al_ = base + GA_SZ;
    const __nv_bfloat16* bh_ = base + 2 * GA_SZ;
    const __nv_bfloat16* bl_ = bh_ + GB_SZ;
    #pragma unroll
    for (int kk = 0; kk < 2; kk++) {
        uint32_t ah4[2][4], al4[2][4];
        const int acol = kk * 16 + ((ln >> 4) << 3);
        #pragma unroll
        for (int mf = 0; mf < 2; mf++) {
            const int arow = wy * 32 + mf * 16 + (ln & 15);
            ldsm4(ah4[mf], sptr(ah_ + arow * GA_LD + acol));
            ldsm4(al4[mf], sptr(al_ + arow * GA_LD + acol));
        }
        #pragma unroll
        for (int np = 0; np < 4; np++) {
            const int brow = kk * 16 + (ln & 7) + (((ln >> 3) & 1) << 3);
            const int bcol = wx * 64 + np * 16 + ((ln >> 4) << 3);
            uint32_t bh4[4], bl4[4];
            ldsm4t(bh4, sptr(bh_ + brow * GB_LD + bcol));
            ldsm4t(bl4, sptr(bl_ + brow * GB_LD + bcol));
            #pragma unroll
            for (int mf = 0; mf < 2; mf++) {
                mma16816(s[mf][2*np],   ah4[mf], bh4[0], bh4[1]);
                mma16816(s[mf][2*np],   al4[mf], bh4[0], bh4[1]);
                mma16816(s[mf][2*np],   ah4[mf], bl4[0], bl4[1]);
                mma16816(s[mf][2*np+1], ah4[mf], bh4[2], bh4[3]);
                mma16816(s[mf][2*np+1], al4[mf], bh4[2], bh4[3]);
                mma16816(s[mf][2*np+1], ah4[mf], bl4[2], bl4[3]);
            }
        }
    }
}

// ---------------------------------------------------------------------------
// Kernel A: QKV projection + RMSNorm + RoPE, outputs bf16 hi/lo Q/K/V.
// grid=(NTOK/128, 12)
// ---------------------------------------------------------------------------
__global__ void __launch_bounds__(256, 2) qkv_kernel(
    const float* __restrict__ cosb, const float* __restrict__ sinb,
    const float* __restrict__ qn_w, const float* __restrict__ kn_w)
{
    extern __shared__ __nv_bfloat16 smg[];
    const int tid = threadIdx.x, ln = tid & 31, wid = tid >> 5;
    const int wy = wid >> 1, wx = wid & 1;
    const int m0 = blockIdx.x * 128;
    const int nblk = blockIdx.y;

    const __nv_bfloat16 *Wh, *Wl; int ldw, kind, hb;
    if (nblk < 8)       { Wh = g_wqh + nblk*128;      Wl = g_wql + nblk*128;      ldw = 1024; kind = 0; hb = nblk*2; }
    else if (nblk < 10) { Wh = g_wkh + (nblk-8)*128;  Wl = g_wkl + (nblk-8)*128;  ldw = 256;  kind = 1; hb = (nblk-8)*2; }
    else                { Wh = g_wvh + (nblk-10)*128; Wl = g_wvl + (nblk-10)*128; ldw = 256;  kind = 2; hb = (nblk-10)*2; }

    const uint32_t smbase = sptr(smg);
    float s[2][8][4] = {};

    gemm_issue(smbase, 0, g_xh + (size_t)m0 * DMODEL, g_xl + (size_t)m0 * DMODEL, DMODEL,
               Wh, Wl, ldw, tid);
    CP_COMMIT;

    int buf = 0;
    for (int k0 = 0; k0 < DMODEL; k0 += 32) {
        CP_WAIT0;
        __syncthreads();
        if (k0 + 32 < DMODEL) {
            gemm_issue(smbase, buf ^ 1,
                       g_xh + (size_t)m0 * DMODEL + k0 + 32,
                       g_xl + (size_t)m0 * DMODEL + k0 + 32, DMODEL,
                       Wh + (size_t)(k0 + 32) * ldw,
                       Wl + (size_t)(k0 + 32) * ldw, ldw, tid);
            CP_COMMIT;
        }
        gemm_compute(smg + buf * GBUF, wy, wx, ln, s);
        buf ^= 1;
    }

    // epilogue: warp (wy,wx) owns rows wy*32..+32, head hb+wx (64 cols)
    const int q2 = (ln & 3) * 2;
    const int h = hb + wx;
    #pragma unroll
    for (int mf = 0; mf < 2; mf++) {
        #pragma unroll
        for (int hf = 0; hf < 2; hf++) {
            const int row = m0 + wy * 32 + mf * 16 + (ln >> 2) + hf * 8;
            const int b = row >> 11, tpos = row & 2047;
            if (kind != 2) {
                const float* nw = (kind == 0) ? qn_w : kn_w;
                float ss = 0.f;
                #pragma unroll
                for (int nf = 0; nf < 8; nf++) {
                    float v0 = s[mf][nf][hf*2], v1 = s[mf][nf][hf*2+1];
                    ss = fmaf(v0, v0, fmaf(v1, v1, ss));
                }
                ss += __shfl_xor_sync(0xffffffffu, ss, 1);
                ss += __shfl_xor_sync(0xffffffffu, ss, 2);
                const float inv = rsqrtf(ss * (1.f/64.f) + 1e-6f);
                #pragma unroll
                for (int j2 = 0; j2 < 4; j2++) {
                    #pragma unroll
                    for (int e = 0; e < 2; e++) {
                        const int hc = 8*j2 + q2 + e;         // 0..31
                        const int p = hf*2 + e;
                        float v1 = s[mf][j2][p]   * inv * nw[hc];
                        float v2 = s[mf][j2+4][p] * inv * nw[hc+32];
                        float cc = cosb[tpos*32 + hc], sn = sinb[tpos*32 + hc];
                        s[mf][j2][p]   = v1*cc - v2*sn;
                        s[mf][j2+4][p] = v2*cc + v1*sn;
                    }
                }
            }
            __nv_bfloat16 *dh, *dl; size_t base;
            if (kind == 0)      { dh = g_qh; dl = g_ql; base = (((size_t)(b*NH  + h))*TT + tpos)*HD; }
            else if (kind == 1) { dh = g_kh; dl = g_kl; base = (((size_t)(b*NKV + h))*TT + tpos)*HD; }
            else                { dh = g_vh; dl = g_vl; base = (((size_t)(b*NKV + h))*TT + tpos)*HD; }
            #pragma unroll
            for (int nf = 0; nf < 8; nf++) {
                const int d = 8*nf + q2;
                float v0 = s[mf][nf][hf*2], v1 = s[mf][nf][hf*2+1];
                __nv_bfloat16 h0 = __float2bfloat16(v0), h1 = __float2bfloat16(v1);
                *(uint32_t*)(dh + base + d) = pkbf(h0, h1);
                *(uint32_t*)(dl + base + d) = pkbf(
                    __float2bfloat16(v0 - __bfloat162float(h0)),
                    __float2bfloat16(v1 - __bfloat162float(h1)));
            }
        }
    }
}

// ---------------------------------------------------------------------------
// Kernel B: causal flash attention. Q frags in registers; K/V hi/lo bf16
// double-buffered via cp.async. grid=(T/128, B*H), 256 threads.
// ---------------------------------------------------------------------------
#define ATT_LD 72
#define ATT_ARR (128*ATT_LD)
#define ATT_STAGE (4*ATT_ARR)
#define ATT_Q_OFF (2*ATT_STAGE)
#define ATTN_SMEM_BYTES ((2*ATT_STAGE + 2*ATT_ARR)*2)

__device__ __forceinline__ void kv_issue(uint32_t smbase, int stage,
    const __nv_bfloat16* Kh, const __nv_bfloat16* Kl,
    const __nv_bfloat16* Vh, const __nv_bfloat16* Vl, int tid)
{
    uint32_t sb = smbase + (uint32_t)stage * (ATT_STAGE * 2);
    #pragma unroll
    for (int it = 0; it < 4; it++) {
        int u = it * 256 + tid; int r = u >> 3, c = (u & 7) * 8;
        size_t off = (size_t)r * HD + c;
        uint32_t d = sb + (r * ATT_LD + c) * 2;
        cpa16(d,               Kh + off);
        cpa16(d + ATT_ARR*2,   Kl + off);
        cpa16(d + 2*ATT_ARR*2, Vh + off);
        cpa16(d + 3*ATT_ARR*2, Vl + off);
    }
}

__global__ void __launch_bounds__(256) attn_kernel()
{
    extern __shared__ __nv_bfloat16 smb[];
    const int tid = threadIdx.x, ln = tid & 31, wid = tid >> 5;
    const int qb = gridDim.x - 1 - blockIdx.x;
    const int bh = blockIdx.y;
    const int b = bh >> 4, h = bh & 15, kvh = h >> 2;
    const uint32_t smbase = sptr(smb);

    const __nv_bfloat16* Qhg = g_qh + ((size_t)(b*NH + h)*TT + qb*128)*HD;
    const __nv_bfloat16* Qlg = g_ql + ((size_t)(b*NH + h)*TT + qb*128)*HD;
    const size_t kvbase = (size_t)(b*NKV + kvh)*TT*HD;

    {
        uint32_t qsb = smbase + ATT_Q_OFF * 2;
        #pragma unroll
        for (int it = 0; it < 4; it++) {
            int u = it * 256 + tid; int r = u >> 3, c = (u & 7) * 8;
            size_t off = (size_t)r * HD + c;
            cpa16(qsb + (r * ATT_LD + c) * 2,           Qhg + off);
            cpa16(qsb + (ATT_ARR + r * ATT_LD + c) * 2, Qlg + off);
        }
    }
    kv_issue(smbase, 0, g_kh + kvbase, g_kl + kvbase, g_vh + kvbase, g_vl + kvbase, tid);
    CP_COMMIT;

    const int mrow = wid * 16;
    const int q2 = (ln & 3) * 2;
    uint32_t qfh[4][4], qfl[4][4];
    float o[8][4] = {};
    float m_i[2] = {-1e30f, -1e30f}, l_i[2] = {0.f, 0.f};

    int buf = 0;
    for (int kb = 0; kb <= qb; kb++) {
        CP_WAIT0;
        __syncthreads();
        if (kb == 0) {
            const __nv_bfloat16* Qh = smb + ATT_Q_OFF;
            const __nv_bfloat16* Ql = Qh + ATT_ARR;
            #pragma unroll
            for (int kk = 0; kk < 4; kk++) {
                const int acol = kk * 16 + ((ln >> 4) << 3);
                ldsm4(qfh[kk], sptr(Qh + (mrow + (ln & 15)) * ATT_LD + acol));
                ldsm4(qfl[kk], sptr(Ql + (mrow + (ln & 15)) * ATT_LD + acol));
            }
        }
        if (kb < qb) {
            size_t o1 = kvbase + (size_t)(kb+1)*128*HD;
            kv_issue(smbase, buf ^ 1, g_kh + o1, g_kl + o1, g_vh + o1, g_vl + o1, tid);
            CP_COMMIT;
        }

        const __nv_bfloat16* Kh = smb + buf * ATT_STAGE;
        const __nv_bfloat16* Kl = Kh + ATT_ARR;
        const __nv_bfloat16* Vh = Kl + ATT_ARR;
        const __nv_bfloat16* Vl = Vh + ATT_ARR;

        float s[16][4];
        #pragma unroll
        for (int f = 0; f < 16; f++) { s[f][0]=0.f; s[f][1]=0.f; s[f][2]=0.f; s[f][3]=0.f; }
        #pragma unroll
        for (int kk = 0; kk < 4; kk++) {
            #pragma unroll
            for (int np = 0; np < 8; np++) {
                const int krow = np*16 + (ln & 7) + ((ln >> 4) << 3);
                const int kcol = kk*16 + (((ln >> 3) & 1) << 3);
                uint32_t bh4[4], bl4[4];
                ldsm4(bh4, sptr(Kh + krow*ATT_LD + kcol));
                ldsm4(bl4, sptr(Kl + krow*ATT_LD + kcol));
                mma16816(s[2*np],   qfh[kk], bh4[0], bh4[1]);
                mma16816(s[2*np],   qfl[kk], bh4[0], bh4[1]);
                mma16816(s[2*np],   qfh[kk], bl4[0], bl4[1]);
                mma16816(s[2*np+1], qfh[kk], bh4[2], bh4[3]);
                mma16816(s[2*np+1], qfl[kk], bh4[2], bh4[3]);
                mma16816(s[2*np+1], qfh[kk], bl4[2], bl4[3]);
            }
        }

        const bool diag = (kb == qb);
        #pragma unroll
        for (int f = 0; f < 16; f++) {
            #pragma unroll
            for (int p = 0; p < 4; p++) {
                float sv = s[f][p] * 0.125f;
                if (diag) {
                    int ck = 8*f + q2 + (p & 1);
                    int rq = mrow + (ln >> 2) + (p >> 1)*8;
                    if (ck > rq) sv = -1e30f;
                }
                s[f][p] = sv;
            }
        }

        float ci[2];
        #pragma unroll
        for (int hf = 0; hf < 2; hf++) {
            float mx = -1e30f;
            #pragma unroll
            for (int f = 0; f < 16; f++)
                mx = fmaxf(mx, fmaxf(s[f][hf*2], s[f][hf*2+1]));
            mx = fmaxf(mx, __shfl_xor_sync(0xffffffffu, mx, 1));
            mx = fmaxf(mx, __shfl_xor_sync(0xffffffffu, mx, 2));
            float mnew = fmaxf(m_i[hf], mx);
            float c = __expf(m_i[hf] - mnew);
            float ps = 0.f;
            #pragma unroll
            for (int f = 0; f < 16; f++) {
                float p0 = __expf(s[f][hf*2]   - mnew);
                float p1 = __expf(s[f][hf*2+1] - mnew);
                s[f][hf*2] = p0; s[f][hf*2+1] = p1;
                ps += p0 + p1;
            }
            ps += __shfl_xor_sync(0xffffffffu, ps, 1);
            ps += __shfl_xor_sync(0xffffffffu, ps, 2);
            l_i[hf] = l_i[hf]*c + ps;
            m_i[hf] = mnew;
            ci[hf] = c;
        }
        #pragma unroll
        for (int f = 0; f < 8; f++) {
            o[f][0] *= ci[0]; o[f][1] *= ci[0];
            o[f][2] *= ci[1]; o[f][3] *= ci[1];
        }

        #pragma unroll
        for (int jj = 0; jj < 8; jj++) {
            uint32_t ph[4], pl[4];
            #pragma unroll
            for (int t = 0; t < 4; t++) {
                const float* src = (t < 2) ? s[2*jj] : s[2*jj+1];
                float v0 = src[(t & 1)*2], v1 = src[(t & 1)*2 + 1];
                __nv_bfloat16 h0 = __float2bfloat16(v0), h1 = __float2bfloat16(v1);
                ph[t] = pkbf(h0, h1);
                pl[t] = pkbf(__float2bfloat16(v0 - __bfloat162float(h0)),
                             __float2bfloat16(v1 - __bfloat162float(h1)));
            }
            #pragma unroll
            for (int dp = 0; dp < 4; dp++) {
                const int vrow = jj*16 + (ln & 7) + (((ln >> 3) & 1) << 3);
                const int vcol = dp*16 + ((ln >> 4) << 3);
                uint32_t vh4[4], vl4[4];
                ldsm4t(vh4, sptr(Vh + vrow*ATT_LD + vcol));
                ldsm4t(vl4, sptr(Vl + vrow*ATT_LD + vcol));
                mma16816(o[2*dp],   ph, vh4[0], vh4[1]);
                mma16816(o[2*dp],   pl, vh4[0], vh4[1]);
                mma16816(o[2*dp],   ph, vl4[0], vl4[1]);
                mma16816(o[2*dp+1], ph, vh4[2], vh4[3]);
                mma16816(o[2*dp+1], pl, vh4[2], vh4[3]);
                mma16816(o[2*dp+1], ph, vl4[2], vl4[3]);
            }
        }
        buf ^= 1;
    }

    #pragma unroll
    for (int hf = 0; hf < 2; hf++) {
        const float inv = 1.0f / l_i[hf];
        const int row = qb*128 + mrow + (ln >> 2) + hf*8;
        const size_t t = (size_t)(b*TT + row);
        #pragma unroll
        for (int f = 0; f < 8; f++) {
            const int d = 8*f + q2;
            float v0 = o[f][hf*2]*inv, v1 = o[f][hf*2+1]*inv;
            __nv_bfloat16 h0 = __float2bfloat16(v0), h1 = __float2bfloat16(v1);
            size_t idx = t*DMODEL + h*HD + d;
            *(uint32_t*)(g_aoh + idx) = pkbf(h0, h1);
            *(uint32_t*)(g_aol + idx) = pkbf(
                __float2bfloat16(v0 - __bfloat162float(h0)),
                __float2bfloat16(v1 - __bfloat162float(h1)));
        }
    }
}

// ---------------------------------------------------------------------------
// Kernel C: output projection. grid=(NTOK/128, DM/128)
// ---------------------------------------------------------------------------
__global__ void __launch_bounds__(256, 2) out_kernel(float* __restrict__ out)
{
    extern __shared__ __nv_bfloat16 smg[];
    const int tid = threadIdx.x, ln = tid & 31, wid = tid >> 5;
    const int wy = wid >> 1, wx = wid & 1;
    const int m0 = blockIdx.x * 128, n0 = blockIdx.y * 128;
    const uint32_t smbase = sptr(smg);
    float s[2][8][4] = {};

    gemm_issue(smbase, 0, g_aoh + (size_t)m0 * DMODEL, g_aol + (size_t)m0 * DMODEL, DMODEL,
               g_woh + n0, g_wol + n0, DMODEL, tid);
    CP_COMMIT;

    int buf = 0;
    for (int k0 = 0; k0 < DMODEL; k0 += 32) {
        CP_WAIT0;
        __syncthreads();
        if (k0 + 32 < DMODEL) {
            gemm_issue(smbase, buf ^ 1,
                       g_aoh + (size_t)m0 * DMODEL + k0 + 32,
                       g_aol + (size_t)m0 * DMODEL + k0 + 32, DMODEL,
                       g_woh + (size_t)(k0 + 32) * DMODEL + n0,
                       g_wol + (size_t)(k0 + 32) * DMODEL + n0, DMODEL, tid);
            CP_COMMIT;
        }
        gemm_compute(smg + buf * GBUF, wy, wx, ln, s);
        buf ^= 1;
    }

    const int q2 = (ln & 3) * 2;
    #pragma unroll
    for (int mf = 0; mf < 2; mf++) {
        #pragma unroll
        for (int hf = 0; hf < 2; hf++) {
            const int row = m0 + wy * 32 + mf * 16 + (ln >> 2) + hf * 8;
            #pragma unroll
            for (int nf = 0; nf < 8; nf++) {
                const int col = n0 + wx * 64 + 8*nf + q2;
                *(float2*)(out + (size_t)row * DMODEL + col) =
                    make_float2(s[mf][nf][hf*2], s[mf][nf][hf*2+1]);
            }
        }
    }
}

// ---------------------------------------------------------------------------
extern "C" void kernel_launch(void* const* d_in, const int* in_sizes, int n_in,
                              void* d_out, int out_size) {
    const float* x    = (const float*)d_in[0];
    const float* cosb = (const float*)d_in[1];
    const float* sinb = (const float*)d_in[2];
    const float* wq   = (const float*)d_in[3];
    const float* wk   = (const float*)d_in[4];
    const float* wv   = (const float*)d_in[5];
    const float* wo   = (const float*)d_in[6];
    const float* qn_w = (const float*)d_in[7];
    const float* kn_w = (const float*)d_in[8];
    float* out = (float*)d_out;

    static int smem_set = 0;
    if (!smem_set) {
        cudaFuncSetAttribute(qkv_kernel,
            cudaFuncAttributeMaxDynamicSharedMemorySize, GEMM_SMEM_BYTES);
        cudaFuncSetAttribute(attn_kernel,
            cudaFuncAttributeMaxDynamicSharedMemorySize, ATTN_SMEM_BYTES);
        cudaFuncSetAttribute(out_kernel,
            cudaFuncAttributeMaxDynamicSharedMemorySize, GEMM_SMEM_BYTES);
        smem_set = 1;
    }

    cvt_kernel<<<2048, 256>>>(x,  0, NTOK*DMODEL/4);
    cvt_kernel<<<1024, 256>>>(wq, 1, DMODEL*NH*HD/4);
    cvt_kernel<<<256,  256>>>(wk, 2, DMODEL*NKV*HD/4);
    cvt_kernel<<<256,  256>>>(wv, 3, DMODEL*NKV*HD/4);
    cvt_kernel<<<1024, 256>>>(wo, 4, NH*HD*DMODEL/4);

    dim3 gA(NTOK / 128, 12);
    qkv_kernel<<<gA, 256, GEMM_SMEM_BYTES>>>(cosb, sinb, qn_w, kn_w);

    dim3 gB(TT / 128, BB * NH);
    attn_kernel<<<gB, 256, ATTN_SMEM_BYTES>>>();

    dim3 gC(NTOK / 128, DMODEL / 128);
    out_kernel<<<gC, 256, GEMM_SMEM_BYTES>>>(out);
}

// round 7
// speedup vs baseline: 4.9516x; 1.3572x over previous
#include <cuda_runtime.h>
#include <cuda_fp16.h>
#include <math.h>
#include <stdint.h>

#define BB 2
#define TT 2048
#define NH 16
#define NKV 4
#define HD 64
#define DMODEL 1024
#define NTOK (BB*TT)

// ---------------- precomputed fp16 operands (device globals) ----------------
// A-side operands split hi/lo; B-side operands hi only.
__device__ __half g_xh[(size_t)NTOK*DMODEL],  g_xl[(size_t)NTOK*DMODEL];
__device__ __half g_wqh[(size_t)DMODEL*NH*HD];
__device__ __half g_wkh[(size_t)DMODEL*NKV*HD];
__device__ __half g_wvh[(size_t)DMODEL*NKV*HD];
__device__ __half g_woh[(size_t)NH*HD*DMODEL];
// intermediates
__device__ __half g_qh[(size_t)BB*NH*TT*HD],  g_ql[(size_t)BB*NH*TT*HD];
__device__ __half g_kh[(size_t)BB*NKV*TT*HD];
__device__ __half g_vh[(size_t)BB*NKV*TT*HD];
__device__ __half g_aoh[(size_t)NTOK*DMODEL], g_aol[(size_t)NTOK*DMODEL];

// ---------------------------------------------------------------------------
// helpers
// ---------------------------------------------------------------------------
__device__ __forceinline__ uint32_t sptr(const void* p) {
    return (uint32_t)__cvta_generic_to_shared(p);
}
__device__ __forceinline__ void ldsm4(uint32_t* r, uint32_t a) {
    asm volatile("ldmatrix.sync.aligned.m8n8.x4.shared.b16 {%0,%1,%2,%3},[%4];"
        : "=r"(r[0]), "=r"(r[1]), "=r"(r[2]), "=r"(r[3]) : "r"(a));
}
__device__ __forceinline__ void ldsm4t(uint32_t* r, uint32_t a) {
    asm volatile("ldmatrix.sync.aligned.m8n8.x4.trans.shared.b16 {%0,%1,%2,%3},[%4];"
        : "=r"(r[0]), "=r"(r[1]), "=r"(r[2]), "=r"(r[3]) : "r"(a));
}
__device__ __forceinline__ void mma16816(float* c, const uint32_t* a,
                                          uint32_t b0, uint32_t b1) {
    asm volatile("mma.sync.aligned.m16n8k16.row.col.f32.f16.f16.f32 "
        "{%0,%1,%2,%3},{%4,%5,%6,%7},{%8,%9},{%0,%1,%2,%3};"
        : "+f"(c[0]), "+f"(c[1]), "+f"(c[2]), "+f"(c[3])
        : "r"(a[0]), "r"(a[1]), "r"(a[2]), "r"(a[3]), "r"(b0), "r"(b1));
}
__device__ __forceinline__ uint32_t pkh(__half a, __half b) {
    return (uint32_t)__half_as_ushort(a) |
           ((uint32_t)__half_as_ushort(b) << 16);
}
// split 4 floats into fp16 hi + fp16 lo
__device__ __forceinline__ void cvt_hl4(float4 v, __half* hp, __half* lp) {
    __half h0 = __float2half_rn(v.x), h1 = __float2half_rn(v.y);
    __half h2 = __float2half_rn(v.z), h3 = __float2half_rn(v.w);
    __half l0 = __float2half_rn(v.x - __half2float(h0));
    __half l1 = __float2half_rn(v.y - __half2float(h1));
    __half l2 = __float2half_rn(v.z - __half2float(h2));
    __half l3 = __float2half_rn(v.w - __half2float(h3));
    ((uint32_t*)hp)[0] = pkh(h0, h1); ((uint32_t*)hp)[1] = pkh(h2, h3);
    ((uint32_t*)lp)[0] = pkh(l0, l1); ((uint32_t*)lp)[1] = pkh(l2, l3);
}
__device__ __forceinline__ void cpa16(uint32_t dst, const void* src) {
    asm volatile("cp.async.cg.shared.global [%0],[%1],16;" :: "r"(dst), "l"(src));
}
#define CP_COMMIT asm volatile("cp.async.commit_group;")
#define CP_WAIT0  asm volatile("cp.async.wait_group 0;")

// ---------------------------------------------------------------------------
// convert kernels
// ---------------------------------------------------------------------------
__global__ __launch_bounds__(256) void cvt_split_kernel(const float* __restrict__ src, int n4) {
    for (int i = blockIdx.x * 256 + threadIdx.x; i < n4; i += gridDim.x * 256) {
        float4 v = ((const float4*)src)[i];
        cvt_hl4(v, g_xh + (size_t)i * 4, g_xl + (size_t)i * 4);
    }
}
__global__ __launch_bounds__(256) void cvt_hi_kernel(const float* __restrict__ src,
                                                     int which, int n4) {
    __half* hi;
    switch (which) {
        case 1: hi = g_wqh; break;
        case 2: hi = g_wkh; break;
        case 3: hi = g_wvh; break;
        default: hi = g_woh; break;
    }
    for (int i = blockIdx.x * 256 + threadIdx.x; i < n4; i += gridDim.x * 256) {
        float4 v = ((const float4*)src)[i];
        __half h0 = __float2half_rn(v.x), h1 = __float2half_rn(v.y);
        __half h2 = __float2half_rn(v.z), h3 = __float2half_rn(v.w);
        ((uint32_t*)(hi + (size_t)i*4))[0] = pkh(h0, h1);
        ((uint32_t*)(hi + (size_t)i*4))[1] = pkh(h2, h3);
    }
}

// ---------------------------------------------------------------------------
// GEMM smem geometry (fp16 elems): per buffer Ah, Al (128x32) + Bh (32x128)
// ---------------------------------------------------------------------------
#define GA_LD 72
#define GB_LD 136
#define GA_SZ (128*GA_LD)
#define GB_SZ (32*GB_LD)
#define GBUF  (2*GA_SZ + GB_SZ)
#define GEMM_SMEM_BYTES (2*GBUF*2)   // 91136

__device__ __forceinline__ void gemm_issue(
    uint32_t smbase, int buf,
    const __half* Ah, const __half* Al, int lda,
    const __half* Bh, int ldb, int tid)
{
    uint32_t ab = smbase + (uint32_t)buf * (GBUF * 2);
    #pragma unroll
    for (int it = 0; it < 2; it++) {                 // A: 128 rows x 32 cols
        int u = it * 256 + tid; int r = u >> 2, c = (u & 3) * 8;
        size_t off = (size_t)r * lda + c;
        cpa16(ab + (r * GA_LD + c) * 2, Ah + off);
        cpa16(ab + (GA_SZ + r * GA_LD + c) * 2, Al + off);
    }
    uint32_t bb = ab + 2 * GA_SZ * 2;
    #pragma unroll
    for (int it = 0; it < 2; it++) {                 // B: 32 rows x 128 cols
        int u = it * 256 + tid; int r = u >> 4, c = (u & 15) * 8;
        cpa16(bb + (r * GB_LD + c) * 2, Bh + (size_t)r * ldb + c);
    }
}

// 4x2 warp tiling: warp (wy,wx) computes rows [wy*32,+32) x cols [wx*64,+64)
__device__ __forceinline__ void gemm_compute(
    const __half* base, int wy, int wx, int ln, float s[2][8][4])
{
    const __half* ah_ = base;
    const __half* al_ = base + GA_SZ;
    const __half* bh_ = base + 2 * GA_SZ;
    #pragma unroll
    for (int kk = 0; kk < 2; kk++) {
        uint32_t ah4[2][4], al4[2][4];
        const int acol = kk * 16 + ((ln >> 4) << 3);
        #pragma unroll
        for (int mf = 0; mf < 2; mf++) {
            const int arow = wy * 32 + mf * 16 + (ln & 15);
            ldsm4(ah4[mf], sptr(ah_ + arow * GA_LD + acol));
            ldsm4(al4[mf], sptr(al_ + arow * GA_LD + acol));
        }
        #pragma unroll
        for (int np = 0; np < 4; np++) {
            const int brow = kk * 16 + (ln & 7) + (((ln >> 3) & 1) << 3);
            const int bcol = wx * 64 + np * 16 + ((ln >> 4) << 3);
            uint32_t bh4[4];
            ldsm4t(bh4, sptr(bh_ + brow * GB_LD + bcol));
            #pragma unroll
            for (int mf = 0; mf < 2; mf++) {
                mma16816(s[mf][2*np],   ah4[mf], bh4[0], bh4[1]);
                mma16816(s[mf][2*np],   al4[mf], bh4[0], bh4[1]);
                mma16816(s[mf][2*np+1], ah4[mf], bh4[2], bh4[3]);
                mma16816(s[mf][2*np+1], al4[mf], bh4[2], bh4[3]);
            }
        }
    }
}

// ---------------------------------------------------------------------------
// Kernel A: QKV projection + RMSNorm + RoPE. Q stored hi/lo, K/V hi only.
// grid=(NTOK/128, 12)
// ---------------------------------------------------------------------------
__global__ void __launch_bounds__(256, 2) qkv_kernel(
    const float* __restrict__ cosb, const float* __restrict__ sinb,
    const float* __restrict__ qn_w, const float* __restrict__ kn_w)
{
    extern __shared__ __half smg[];
    const int tid = threadIdx.x, ln = tid & 31, wid = tid >> 5;
    const int wy = wid >> 1, wx = wid & 1;
    const int m0 = blockIdx.x * 128;
    const int nblk = blockIdx.y;

    const __half* Wh; int ldw, kind, hb;
    if (nblk < 8)       { Wh = g_wqh + nblk*128;      ldw = 1024; kind = 0; hb = nblk*2; }
    else if (nblk < 10) { Wh = g_wkh + (nblk-8)*128;  ldw = 256;  kind = 1; hb = (nblk-8)*2; }
    else                { Wh = g_wvh + (nblk-10)*128; ldw = 256;  kind = 2; hb = (nblk-10)*2; }

    const uint32_t smbase = sptr(smg);
    float s[2][8][4] = {};

    gemm_issue(smbase, 0, g_xh + (size_t)m0 * DMODEL, g_xl + (size_t)m0 * DMODEL, DMODEL,
               Wh, ldw, tid);
    CP_COMMIT;

    int buf = 0;
    for (int k0 = 0; k0 < DMODEL; k0 += 32) {
        CP_WAIT0;
        __syncthreads();
        if (k0 + 32 < DMODEL) {
            gemm_issue(smbase, buf ^ 1,
                       g_xh + (size_t)m0 * DMODEL + k0 + 32,
                       g_xl + (size_t)m0 * DMODEL + k0 + 32, DMODEL,
                       Wh + (size_t)(k0 + 32) * ldw, ldw, tid);
            CP_COMMIT;
        }
        gemm_compute(smg + buf * GBUF, wy, wx, ln, s);
        buf ^= 1;
    }

    // epilogue: warp (wy,wx) owns rows wy*32..+32, head hb+wx (64 cols)
    const int q2 = (ln & 3) * 2;
    const int h = hb + wx;
    #pragma unroll
    for (int mf = 0; mf < 2; mf++) {
        #pragma unroll
        for (int hf = 0; hf < 2; hf++) {
            const int row = m0 + wy * 32 + mf * 16 + (ln >> 2) + hf * 8;
            const int b = row >> 11, tpos = row & 2047;
            if (kind != 2) {
                const float* nw = (kind == 0) ? qn_w : kn_w;
                float ss = 0.f;
                #pragma unroll
                for (int nf = 0; nf < 8; nf++) {
                    float v0 = s[mf][nf][hf*2], v1 = s[mf][nf][hf*2+1];
                    ss = fmaf(v0, v0, fmaf(v1, v1, ss));
                }
                ss += __shfl_xor_sync(0xffffffffu, ss, 1);
                ss += __shfl_xor_sync(0xffffffffu, ss, 2);
                const float inv = rsqrtf(ss * (1.f/64.f) + 1e-6f);
                #pragma unroll
                for (int j2 = 0; j2 < 4; j2++) {
                    #pragma unroll
                    for (int e = 0; e < 2; e++) {
                        const int hc = 8*j2 + q2 + e;
                        const int p = hf*2 + e;
                        float v1 = s[mf][j2][p]   * inv * nw[hc];
                        float v2 = s[mf][j2+4][p] * inv * nw[hc+32];
                        float cc = cosb[tpos*32 + hc], sn = sinb[tpos*32 + hc];
                        s[mf][j2][p]   = v1*cc - v2*sn;
                        s[mf][j2+4][p] = v2*cc + v1*sn;
                    }
                }
            }
            #pragma unroll
            for (int nf = 0; nf < 8; nf++) {
                const int d = 8*nf + q2;
                float v0 = s[mf][nf][hf*2], v1 = s[mf][nf][hf*2+1];
                __half h0 = __float2half_rn(v0), h1 = __float2half_rn(v1);
                if (kind == 0) {
                    size_t base = (((size_t)(b*NH + h))*TT + tpos)*HD + d;
                    *(uint32_t*)(g_qh + base) = pkh(h0, h1);
                    *(uint32_t*)(g_ql + base) = pkh(
                        __float2half_rn(v0 - __half2float(h0)),
                        __float2half_rn(v1 - __half2float(h1)));
                } else {
                    size_t base = (((size_t)(b*NKV + h))*TT + tpos)*HD + d;
                    __half* dst = (kind == 1) ? g_kh : g_vh;
                    *(uint32_t*)(dst + base) = pkh(h0, h1);
                }
            }
        }
    }
}

// ---------------------------------------------------------------------------
// Kernel B: causal flash attention. Q hi/lo frags in registers; K/V hi-only
// double-buffered via cp.async. grid=(T/128, B*H), 256 threads.
// ---------------------------------------------------------------------------
#define ATT_LD 72
#define ATT_ARR (128*ATT_LD)
#define ATT_STAGE (2*ATT_ARR)           // Kh, Vh
#define ATT_Q_OFF (2*ATT_STAGE)         // then Qh, Ql
#define ATTN_SMEM_BYTES ((2*ATT_STAGE + 2*ATT_ARR)*2)   // 110592

__device__ __forceinline__ void kv_issue(uint32_t smbase, int stage,
    const __half* Kh, const __half* Vh, int tid)
{
    uint32_t sb = smbase + (uint32_t)stage * (ATT_STAGE * 2);
    #pragma unroll
    for (int it = 0; it < 4; it++) {
        int u = it * 256 + tid; int r = u >> 3, c = (u & 7) * 8;
        size_t off = (size_t)r * HD + c;
        uint32_t d = sb + (r * ATT_LD + c) * 2;
        cpa16(d,             Kh + off);
        cpa16(d + ATT_ARR*2, Vh + off);
    }
}

__global__ void __launch_bounds__(256) attn_kernel()
{
    extern __shared__ __half smb[];
    const int tid = threadIdx.x, ln = tid & 31, wid = tid >> 5;
    const int qb = gridDim.x - 1 - blockIdx.x;
    const int bh = blockIdx.y;
    const int b = bh >> 4, h = bh & 15, kvh = h >> 2;
    const uint32_t smbase = sptr(smb);

    const __half* Qhg = g_qh + ((size_t)(b*NH + h)*TT + qb*128)*HD;
    const __half* Qlg = g_ql + ((size_t)(b*NH + h)*TT + qb*128)*HD;
    const size_t kvbase = (size_t)(b*NKV + kvh)*TT*HD;

    {
        uint32_t qsb = smbase + ATT_Q_OFF * 2;
        #pragma unroll
        for (int it = 0; it < 4; it++) {
            int u = it * 256 + tid; int r = u >> 3, c = (u & 7) * 8;
            size_t off = (size_t)r * HD + c;
            cpa16(qsb + (r * ATT_LD + c) * 2,           Qhg + off);
            cpa16(qsb + (ATT_ARR + r * ATT_LD + c) * 2, Qlg + off);
        }
    }
    kv_issue(smbase, 0, g_kh + kvbase, g_vh + kvbase, tid);
    CP_COMMIT;

    const int mrow = wid * 16;
    const int q2 = (ln & 3) * 2;
    uint32_t qfh[4][4], qfl[4][4];
    float o[8][4] = {};
    float m_i[2] = {-1e30f, -1e30f}, l_i[2] = {0.f, 0.f};

    int buf = 0;
    for (int kb = 0; kb <= qb; kb++) {
        CP_WAIT0;
        __syncthreads();
        if (kb == 0) {
            const __half* Qh = smb + ATT_Q_OFF;
            const __half* Ql = Qh + ATT_ARR;
            #pragma unroll
            for (int kk = 0; kk < 4; kk++) {
                const int acol = kk * 16 + ((ln >> 4) << 3);
                ldsm4(qfh[kk], sptr(Qh + (mrow + (ln & 15)) * ATT_LD + acol));
                ldsm4(qfl[kk], sptr(Ql + (mrow + (ln & 15)) * ATT_LD + acol));
            }
        }
        if (kb < qb) {
            size_t o1 = kvbase + (size_t)(kb+1)*128*HD;
            kv_issue(smbase, buf ^ 1, g_kh + o1, g_vh + o1, tid);
            CP_COMMIT;
        }

        const __half* Kh = smb + buf * ATT_STAGE;
        const __half* Vh = Kh + ATT_ARR;

        // S = Q K^T  (2-term split)
        float s[16][4];
        #pragma unroll
        for (int f = 0; f < 16; f++) { s[f][0]=0.f; s[f][1]=0.f; s[f][2]=0.f; s[f][3]=0.f; }
        #pragma unroll
        for (int kk = 0; kk < 4; kk++) {
            #pragma unroll
            for (int np = 0; np < 8; np++) {
                const int krow = np*16 + (ln & 7) + ((ln >> 4) << 3);
                const int kcol = kk*16 + (((ln >> 3) & 1) << 3);
                uint32_t bh4[4];
                ldsm4(bh4, sptr(Kh + krow*ATT_LD + kcol));
                mma16816(s[2*np],   qfh[kk], bh4[0], bh4[1]);
                mma16816(s[2*np],   qfl[kk], bh4[0], bh4[1]);
                mma16816(s[2*np+1], qfh[kk], bh4[2], bh4[3]);
                mma16816(s[2*np+1], qfl[kk], bh4[2], bh4[3]);
            }
        }

        const bool diag = (kb == qb);
        #pragma unroll
        for (int f = 0; f < 16; f++) {
            #pragma unroll
            for (int p = 0; p < 4; p++) {
                float sv = s[f][p] * 0.125f;
                if (diag) {
                    int ck = 8*f + q2 + (p & 1);
                    int rq = mrow + (ln >> 2) + (p >> 1)*8;
                    if (ck > rq) sv = -1e30f;
                }
                s[f][p] = sv;
            }
        }

        float ci[2];
        #pragma unroll
        for (int hf = 0; hf < 2; hf++) {
            float mx = -1e30f;
            #pragma unroll
            for (int f = 0; f < 16; f++)
                mx = fmaxf(mx, fmaxf(s[f][hf*2], s[f][hf*2+1]));
            mx = fmaxf(mx, __shfl_xor_sync(0xffffffffu, mx, 1));
            mx = fmaxf(mx, __shfl_xor_sync(0xffffffffu, mx, 2));
            float mnew = fmaxf(m_i[hf], mx);
            float c = __expf(m_i[hf] - mnew);
            float ps = 0.f;
            #pragma unroll
            for (int f = 0; f < 16; f++) {
                float p0 = __expf(s[f][hf*2]   - mnew);
                float p1 = __expf(s[f][hf*2+1] - mnew);
                s[f][hf*2] = p0; s[f][hf*2+1] = p1;
                ps += p0 + p1;
            }
            ps += __shfl_xor_sync(0xffffffffu, ps, 1);
            ps += __shfl_xor_sync(0xffffffffu, ps, 2);
            l_i[hf] = l_i[hf]*c + ps;
            m_i[hf] = mnew;
            ci[hf] = c;
        }
        #pragma unroll
        for (int f = 0; f < 8; f++) {
            o[f][0] *= ci[0]; o[f][1] *= ci[0];
            o[f][2] *= ci[1]; o[f][3] *= ci[1];
        }

        // O += P V  (P split in registers, V hi only)
        #pragma unroll
        for (int jj = 0; jj < 8; jj++) {
            uint32_t ph[4], pl[4];
            #pragma unroll
            for (int t = 0; t < 4; t++) {
                const float* src = (t < 2) ? s[2*jj] : s[2*jj+1];
                float v0 = src[(t & 1)*2], v1 = src[(t & 1)*2 + 1];
                __half h0 = __float2half_rn(v0), h1 = __float2half_rn(v1);
                ph[t] = pkh(h0, h1);
                pl[t] = pkh(__float2half_rn(v0 - __half2float(h0)),
                            __float2half_rn(v1 - __half2float(h1)));
            }
            #pragma unroll
            for (int dp = 0; dp < 4; dp++) {
                const int vrow = jj*16 + (ln & 7) + (((ln >> 3) & 1) << 3);
                const int vcol = dp*16 + ((ln >> 4) << 3);
                uint32_t vh4[4];
                ldsm4t(vh4, sptr(Vh + vrow*ATT_LD + vcol));
                mma16816(o[2*dp],   ph, vh4[0], vh4[1]);
                mma16816(o[2*dp],   pl, vh4[0], vh4[1]);
                mma16816(o[2*dp+1], ph, vh4[2], vh4[3]);
                mma16816(o[2*dp+1], pl, vh4[2], vh4[3]);
            }
        }
        buf ^= 1;
    }

    #pragma unroll
    for (int hf = 0; hf < 2; hf++) {
        const float inv = 1.0f / l_i[hf];
        const int row = qb*128 + mrow + (ln >> 2) + hf*8;
        const size_t t = (size_t)(b*TT + row);
        #pragma unroll
        for (int f = 0; f < 8; f++) {
            const int d = 8*f + q2;
            float v0 = o[f][hf*2]*inv, v1 = o[f][hf*2+1]*inv;
            __half h0 = __float2half_rn(v0), h1 = __float2half_rn(v1);
            size_t idx = t*DMODEL + h*HD + d;
            *(uint32_t*)(g_aoh + idx) = pkh(h0, h1);
            *(uint32_t*)(g_aol + idx) = pkh(
                __float2half_rn(v0 - __half2float(h0)),
                __float2half_rn(v1 - __half2float(h1)));
        }
    }
}

// ---------------------------------------------------------------------------
// Kernel C: output projection. grid=(NTOK/128, DM/128)
// ---------------------------------------------------------------------------
__global__ void __launch_bounds__(256, 2) out_kernel(float* __restrict__ out)
{
    extern __shared__ __half smg[];
    const int tid = threadIdx.x, ln = tid & 31, wid = tid >> 5;
    const int wy = wid >> 1, wx = wid & 1;
    const int m0 = blockIdx.x * 128, n0 = blockIdx.y * 128;
    const uint32_t smbase = sptr(smg);
    float s[2][8][4] = {};

    gemm_issue(smbase, 0, g_aoh + (size_t)m0 * DMODEL, g_aol + (size_t)m0 * DMODEL, DMODEL,
               g_woh + n0, DMODEL, tid);
    CP_COMMIT;

    int buf = 0;
    for (int k0 = 0; k0 < DMODEL; k0 += 32) {
        CP_WAIT0;
        __syncthreads();
        if (k0 + 32 < DMODEL) {
            gemm_issue(smbase, buf ^ 1,
                       g_aoh + (size_t)m0 * DMODEL + k0 + 32,
                       g_aol + (size_t)m0 * DMODEL + k0 + 32, DMODEL,
                       g_woh + (size_t)(k0 + 32) * DMODEL + n0, DMODEL, tid);
            CP_COMMIT;
        }
        gemm_compute(smg + buf * GBUF, wy, wx, ln, s);
        buf ^= 1;
    }

    const int q2 = (ln & 3) * 2;
    #pragma unroll
    for (int mf = 0; mf < 2; mf++) {
        #pragma unroll
        for (int hf = 0; hf < 2; hf++) {
            const int row = m0 + wy * 32 + mf * 16 + (ln >> 2) + hf * 8;
            #pragma unroll
            for (int nf = 0; nf < 8; nf++) {
                const int col = n0 + wx * 64 + 8*nf + q2;
                *(float2*)(out + (size_t)row * DMODEL + col) =
                    make_float2(s[mf][nf][hf*2], s[mf][nf][hf*2+1]);
            }
        }
    }
}

// ---------------------------------------------------------------------------
extern "C" void kernel_launch(void* const* d_in, const int* in_sizes, int n_in,
                              void* d_out, int out_size) {
    const float* x    = (const float*)d_in[0];
    const float* cosb = (const float*)d_in[1];
    const float* sinb = (const float*)d_in[2];
    const float* wq   = (const float*)d_in[3];
    const float* wk   = (const float*)d_in[4];
    const float* wv   = (const float*)d_in[5];
    const float* wo   = (const float*)d_in[6];
    const float* qn_w = (const float*)d_in[7];
    const float* kn_w = (const float*)d_in[8];
    float* out = (float*)d_out;

    static int smem_set = 0;
    if (!smem_set) {
        cudaFuncSetAttribute(qkv_kernel,
            cudaFuncAttributeMaxDynamicSharedMemorySize, GEMM_SMEM_BYTES);
        cudaFuncSetAttribute(attn_kernel,
            cudaFuncAttributeMaxDynamicSharedMemorySize, ATTN_SMEM_BYTES);
        cudaFuncSetAttribute(out_kernel,
            cudaFuncAttributeMaxDynamicSharedMemorySize, GEMM_SMEM_BYTES);
        smem_set = 1;
    }

    cvt_split_kernel<<<2048, 256>>>(x, NTOK*DMODEL/4);
    cvt_hi_kernel<<<1024, 256>>>(wq, 1, DMODEL*NH*HD/4);
    cvt_hi_kernel<<<256,  256>>>(wk, 2, DMODEL*NKV*HD/4);
    cvt_hi_kernel<<<256,  256>>>(wv, 3, DMODEL*NKV*HD/4);
    cvt_hi_kernel<<<1024, 256>>>(wo, 4, NH*HD*DMODEL/4);

    dim3 gA(NTOK / 128, 12);
    qkv_kernel<<<gA, 256, GEMM_SMEM_BYTES>>>(cosb, sinb, qn_w, kn_w);

    dim3 gB(TT / 128, BB * NH);
    attn_kernel<<<gB, 256, ATTN_SMEM_BYTES>>>();

    dim3 gC(NTOK / 128, DMODEL / 128);
    out_kernel<<<gC, 256, GEMM_SMEM_BYTES>>>(out);
}